// round 10
// baseline (speedup 1.0000x reference)
#include <cuda_runtime.h>
#include <cuda_bf16.h>
#include <cstdint>

// ---------------------------------------------------------------------------
// Round 9 (clean R7): packed sort records + int4 hist + 3-stage cp.async TC.
//   w = relu(attn);  A_norm^T @ Y == dis ⊙ ( w^T @ (dis ⊙ Y) )
//   convert pass: Ah/Al = bf16 split of relu(attn), + deg partials (fused)
//   P  = dis ⊙ (emb[node_idx] @ W1)        (SIMT fp32 -> bf16 hi/lo)
//   H  = relu(dis ⊙ Σ(w^T @ P) + b1)       (TC split-K=2 + reduce)
//   Q  = dis ⊙ (H @ W2)                    (SIMT fp32 -> bf16 hi/lo)
//   Z  = dis ⊙ Σ(w^T @ Q) + b2            (TC split-K=4 + reduce)
//   decode: bucket-sort edges by src (packed int2), smem-cached z[src]
// ---------------------------------------------------------------------------

static constexpr int N_NODES = 8192;
static constexpr int E_DIM_C = 256;
static constexpr int HID_C   = 256;
static constexpr int OUT_C   = 128;
static constexpr int MAX_PRED = 2100000;

__device__ float          g_degp[64 * N_NODES];
__device__ float          g_dis [N_NODES];
__device__ __nv_bfloat16  g_Ah  [(size_t)N_NODES * N_NODES];
__device__ __nv_bfloat16  g_Al  [(size_t)N_NODES * N_NODES];
__device__ __nv_bfloat16  g_Bh  [N_NODES * HID_C];
__device__ __nv_bfloat16  g_Bl  [N_NODES * HID_C];
__device__ float          g_H   [N_NODES * HID_C];
__device__ float          g_Z   [N_NODES * OUT_C];
__device__ float          g_part[2 * N_NODES * HID_C];
// decode sort scratch
__device__ int            g_cnt  [N_NODES];
__device__ int            g_start[N_NODES + 1];
__device__ int            g_cur  [N_NODES];
__device__ int2           g_sde  [MAX_PRED];     // .x = dst, .y = eid

// ---------------------------------------------------------------------------
__device__ __forceinline__ uint32_t packbf2(float a, float b)
{
    __nv_bfloat162 t(__float2bfloat16(a), __float2bfloat16(b));
    return *reinterpret_cast<uint32_t*>(&t);
}
__device__ __forceinline__ float bf16of(float x)
{
    return __bfloat162float(__float2bfloat16(x));
}

// ---------------------------------------------------------------------------
// Fused convert + deg: read attn once; write relu'd hi/lo bf16; col partials.
// ---------------------------------------------------------------------------
__global__ void convert_deg_kernel(const float* __restrict__ attn)
{
    int c4 = blockIdx.x * blockDim.x + threadIdx.x;
    int r0 = blockIdx.y * 128;
    float4 s = make_float4(0.f, 0.f, 0.f, 0.f);
    const float4* a = reinterpret_cast<const float4*>(attn);
    #pragma unroll 4
    for (int r = 0; r < 128; ++r) {
        size_t row = r0 + r;
        float4 v = a[row * (N_NODES / 4) + c4];
        v.x = fmaxf(v.x, 0.f); v.y = fmaxf(v.y, 0.f);
        v.z = fmaxf(v.z, 0.f); v.w = fmaxf(v.w, 0.f);
        s.x += v.x; s.y += v.y; s.z += v.z; s.w += v.w;
        uint2 h, l;
        h.x = packbf2(v.x, v.y);
        h.y = packbf2(v.z, v.w);
        l.x = packbf2(v.x - bf16of(v.x), v.y - bf16of(v.y));
        l.y = packbf2(v.z - bf16of(v.z), v.w - bf16of(v.w));
        size_t off = (row * N_NODES) / 4 + c4;
        reinterpret_cast<uint2*>(g_Ah)[off] = h;
        reinterpret_cast<uint2*>(g_Al)[off] = l;
    }
    reinterpret_cast<float4*>(g_degp)[blockIdx.y * (N_NODES / 4) + c4] = s;
}

__global__ void dis_kernel()
{
    int col = blockIdx.x * blockDim.x + threadIdx.x;
    float s = 0.f;
    #pragma unroll
    for (int r = 0; r < 64; ++r) s += g_degp[r * N_NODES + col];
    g_dis[col] = (s > 0.f) ? rsqrtf(s) : 0.f;
}

// ---------------------------------------------------------------------------
__device__ __forceinline__ void ldsm_x4_t(uint32_t& r0, uint32_t& r1,
                                          uint32_t& r2, uint32_t& r3, uint32_t addr)
{
    asm volatile("ldmatrix.sync.aligned.m8n8.x4.trans.shared.b16 {%0,%1,%2,%3}, [%4];"
                 : "=r"(r0), "=r"(r1), "=r"(r2), "=r"(r3) : "r"(addr));
}

__device__ __forceinline__ void mma16816(float* d, const uint32_t* a, const uint32_t* b)
{
    asm volatile("mma.sync.aligned.m16n8k16.row.col.f32.bf16.bf16.f32 "
                 "{%0,%1,%2,%3}, {%4,%5,%6,%7}, {%8,%9}, {%0,%1,%2,%3};"
                 : "+f"(d[0]), "+f"(d[1]), "+f"(d[2]), "+f"(d[3])
                 : "r"(a[0]), "r"(a[1]), "r"(a[2]), "r"(a[3]), "r"(b[0]), "r"(b[1]));
}

__device__ __forceinline__ void cpasync16(uint32_t smem, const void* gmem)
{
    asm volatile("cp.async.cg.shared.global [%0], [%1], 16;" :: "r"(smem), "l"(gmem));
}

// ---------------------------------------------------------------------------
// TC GEMM on pre-converted bf16 (3-MMA hi/lo split), 3-stage cp.async,
// 2 CTAs/SM.  Ah/Al: [K, M] bf16, Bh/Bl: [K, N] bf16, both row-major.
// BM=128, BN=128, BK=32, 256 threads, warp tile 64x32.
// ---------------------------------------------------------------------------
template<int SPLITK>
__global__ __launch_bounds__(256, 2)
void tc_gemm(const __nv_bfloat16* __restrict__ Ahg,
             const __nv_bfloat16* __restrict__ Alg,
             const __nv_bfloat16* __restrict__ Bhg,
             const __nv_bfloat16* __restrict__ Blg,
             float* __restrict__ Cpart, int M, int N, int K)
{
    constexpr int BM = 128, BN = 128, BK = 32;
    constexpr int AP = 136;
    constexpr int STG = BK * AP;          // bf16 elems per plane per stage
    constexpr int NSTAGE = 3;

    extern __shared__ __nv_bfloat16 smheap[];
    auto plane = [&](int s, int p) { return smheap + (s * 4 + p) * STG; };

    const int tid  = threadIdx.x;
    const int lane = tid & 31;
    const int wid  = tid >> 5;
    const int wm   = (wid >> 2) * 64;
    const int wn   = (wid & 3) * 32;
    const int m0   = blockIdx.y * BM;
    const int n0   = blockIdx.x * BN;
    const int Ksp  = K / SPLITK;
    const int kB   = blockIdx.z * Ksp;
    const int KT   = Ksp / BK;

    float acc[4][4][4];
    #pragma unroll
    for (int i = 0; i < 4; ++i)
        #pragma unroll
        for (int j = 0; j < 4; ++j)
            #pragma unroll
            for (int q = 0; q < 4; ++q) acc[i][j][q] = 0.f;

    auto issue = [&](int kt, int s) {
        int kg = kB + kt * BK;
        uint32_t base = (uint32_t)__cvta_generic_to_shared(plane(s, 0));
        #pragma unroll
        for (int v = 0; v < 2; ++v) {
            int idx  = tid + v * 256;
            int row  = idx >> 4;
            int c16  = idx & 15;
            uint32_t so = row * (AP * 2) + c16 * 16;
            size_t   aoff = (size_t)(kg + row) * M + m0 + c16 * 8;
            size_t   boff = (size_t)(kg + row) * N + n0 + c16 * 8;
            cpasync16(base + 0 * STG * 2 + so, Ahg + aoff);
            cpasync16(base + 1 * STG * 2 + so, Alg + aoff);
            cpasync16(base + 2 * STG * 2 + so, Bhg + boff);
            cpasync16(base + 3 * STG * 2 + so, Blg + boff);
        }
        asm volatile("cp.async.commit_group;");
    };

    const int aRow = (lane & 7) + ((lane >> 4) & 1) * 8;
    const int aCol = wm + ((lane >> 3) & 1) * 8;
    const int bRow = (lane & 7) + ((lane >> 3) & 1) * 8;
    const int bCol = wn + ((lane >> 4) & 1) * 8;

    auto compute = [&](int s) {
        uint32_t ahB = (uint32_t)__cvta_generic_to_shared(plane(s, 0));
        uint32_t alB = (uint32_t)__cvta_generic_to_shared(plane(s, 1));
        uint32_t bhB = (uint32_t)__cvta_generic_to_shared(plane(s, 2));
        uint32_t blB = (uint32_t)__cvta_generic_to_shared(plane(s, 3));
        #pragma unroll
        for (int k16 = 0; k16 < 2; ++k16) {
            int k0 = k16 * 16;
            uint32_t bhf[4][2], blf[4][2];
            #pragma unroll
            for (int p = 0; p < 2; ++p) {
                uint32_t off = ((k0 + bRow) * AP + bCol + p * 16) * 2;
                uint32_t r0, r1, r2, r3;
                ldsm_x4_t(r0, r1, r2, r3, bhB + off);
                bhf[2 * p][0] = r0; bhf[2 * p][1] = r1;
                bhf[2 * p + 1][0] = r2; bhf[2 * p + 1][1] = r3;
                ldsm_x4_t(r0, r1, r2, r3, blB + off);
                blf[2 * p][0] = r0; blf[2 * p][1] = r1;
                blf[2 * p + 1][0] = r2; blf[2 * p + 1][1] = r3;
            }
            #pragma unroll
            for (int mi = 0; mi < 4; ++mi) {
                uint32_t ahf[4], alf[4];
                uint32_t off = ((k0 + aRow) * AP + aCol + mi * 16) * 2;
                ldsm_x4_t(ahf[0], ahf[1], ahf[2], ahf[3], ahB + off);
                ldsm_x4_t(alf[0], alf[1], alf[2], alf[3], alB + off);
                #pragma unroll
                for (int ni = 0; ni < 4; ++ni) {
                    mma16816(acc[mi][ni], ahf, bhf[ni]);
                    mma16816(acc[mi][ni], ahf, blf[ni]);
                    mma16816(acc[mi][ni], alf, bhf[ni]);
                }
            }
        }
    };

    // prologue: fill the pipeline
    issue(0, 0);
    if (KT > 1) issue(1, 1);
    if (KT > 2) issue(2, 2);

    for (int kt = 0; kt < KT; ++kt) {
        // ensure group kt landed: allow NSTAGE-2 younger groups pending
        asm volatile("cp.async.wait_group %0;" :: "n"(NSTAGE - 2));
        __syncthreads();
        compute(kt % NSTAGE);
        __syncthreads();
        if (kt + NSTAGE < KT) {
            issue(kt + NSTAGE, kt % NSTAGE);   // refill stage just consumed
        } else if (kt + 1 < KT) {
            // keep group accounting aligned: commit an empty group
            asm volatile("cp.async.commit_group;");
        }
    }

    float* Cp = Cpart + (size_t)blockIdx.z * M * N;
    const int rB = m0 + wm + (lane >> 2);
    const int cB = n0 + wn + (lane & 3) * 2;
    #pragma unroll
    for (int mi = 0; mi < 4; ++mi)
        #pragma unroll
        for (int ni = 0; ni < 4; ++ni) {
            int r = rB + mi * 16;
            int c = cB + ni * 8;
            *reinterpret_cast<float2*>(Cp + (size_t)r * N + c) =
                make_float2(acc[mi][ni][0], acc[mi][ni][1]);
            *reinterpret_cast<float2*>(Cp + (size_t)(r + 8) * N + c) =
                make_float2(acc[mi][ni][2], acc[mi][ni][3]);
        }
}

// ---------------------------------------------------------------------------
template<int SPLITK, bool RELU>
__global__ void reduce_epi_kernel(const float* __restrict__ part,
                                  const float* __restrict__ bias,
                                  float* __restrict__ C, int N)
{
    int i4 = blockIdx.x * blockDim.x + threadIdx.x;
    int MN4 = N_NODES * N / 4;
    if (i4 >= MN4) return;
    const float4* p = reinterpret_cast<const float4*>(part);
    float4 s = p[i4];
    #pragma unroll
    for (int sp = 1; sp < SPLITK; ++sp) {
        float4 v = p[i4 + (size_t)sp * MN4];
        s.x += v.x; s.y += v.y; s.z += v.z; s.w += v.w;
    }
    int row = (i4 * 4) / N;
    int col = (i4 * 4) % N;
    float sc = g_dis[row];
    float4 bb = *reinterpret_cast<const float4*>(bias + col);
    float4 r;
    r.x = s.x * sc + bb.x;
    r.y = s.y * sc + bb.y;
    r.z = s.z * sc + bb.z;
    r.w = s.w * sc + bb.w;
    if (RELU) {
        r.x = fmaxf(r.x, 0.f); r.y = fmaxf(r.y, 0.f);
        r.z = fmaxf(r.z, 0.f); r.w = fmaxf(r.w, 0.f);
    }
    reinterpret_cast<float4*>(C)[i4] = r;
}

// ---------------------------------------------------------------------------
// SIMT fp32 GEMM; epilogue writes bf16 hi/lo planes.
// ---------------------------------------------------------------------------
template<int BM, int BN, int BK, int TM, int TN, bool GATHER_A>
__global__ __launch_bounds__((BM / TM) * (BN / TN))
void simt_gemm(const float* __restrict__ A, int lda,
               const float* __restrict__ B,
               __nv_bfloat16* __restrict__ Ch,
               __nv_bfloat16* __restrict__ Cl,
               float* __restrict__ Cf,
               const float* __restrict__ rowScale,
               const int* __restrict__ gatherIdx,
               int M, int N, int K)
{
    constexpr int NT   = (BM / TM) * (BN / TN);
    constexpr int APAD = 4;
    constexpr int AV   = (BM * BK) / (4 * NT);
    constexpr int BV   = (BK * BN) / (4 * NT);

    __shared__ float As[BK][BM + APAD];
    __shared__ float Bs[BK][BN];

    const int tid = threadIdx.x;
    const int tx  = tid % (BN / TN);
    const int ty  = tid / (BN / TN);
    const int m0  = blockIdx.y * BM;
    const int n0  = blockIdx.x * BN;

    float4 areg[AV], breg[BV];
    float acc[TM][TN];
    #pragma unroll
    for (int i = 0; i < TM; ++i)
        #pragma unroll
        for (int j = 0; j < TN; ++j) acc[i][j] = 0.f;

    auto loadA = [&](int k0) {
        #pragma unroll
        for (int v = 0; v < AV; ++v) {
            int idx = tid + v * NT;
            int m  = idx / (BK / 4);
            int kq = idx % (BK / 4);
            int row = GATHER_A ? gatherIdx[m0 + m] : (m0 + m);
            areg[v] = *reinterpret_cast<const float4*>(A + (size_t)row * lda + (k0 + kq * 4));
        }
    };
    auto storeA = [&]() {
        #pragma unroll
        for (int v = 0; v < AV; ++v) {
            int idx = tid + v * NT;
            int m  = idx / (BK / 4);
            int kq = idx % (BK / 4);
            As[kq * 4 + 0][m] = areg[v].x;
            As[kq * 4 + 1][m] = areg[v].y;
            As[kq * 4 + 2][m] = areg[v].z;
            As[kq * 4 + 3][m] = areg[v].w;
        }
    };
    auto loadB = [&](int k0) {
        #pragma unroll
        for (int v = 0; v < BV; ++v) {
            int idx = tid + v * NT;
            int k  = idx / (BN / 4);
            int n4 = idx % (BN / 4);
            breg[v] = *reinterpret_cast<const float4*>(B + (size_t)(k0 + k) * N + (n0 + n4 * 4));
        }
    };
    auto storeB = [&]() {
        #pragma unroll
        for (int v = 0; v < BV; ++v) {
            int idx = tid + v * NT;
            int k  = idx / (BN / 4);
            int n4 = idx % (BN / 4);
            *reinterpret_cast<float4*>(&Bs[k][n4 * 4]) = breg[v];
        }
    };

    loadA(0); loadB(0);
    storeA(); storeB();
    __syncthreads();

    const int KT = K / BK;
    for (int kt = 0; kt < KT; ++kt) {
        if (kt + 1 < KT) { loadA((kt + 1) * BK); loadB((kt + 1) * BK); }
        #pragma unroll
        for (int kk = 0; kk < BK; ++kk) {
            float a[TM], b[TN];
            #pragma unroll
            for (int i = 0; i < TM; i += 4) {
                float4 t = *reinterpret_cast<const float4*>(&As[kk][ty * TM + i]);
                a[i] = t.x; a[i + 1] = t.y; a[i + 2] = t.z; a[i + 3] = t.w;
            }
            #pragma unroll
            for (int j = 0; j < TN; j += 4) {
                float4 t = *reinterpret_cast<const float4*>(&Bs[kk][tx * TN + j]);
                b[j] = t.x; b[j + 1] = t.y; b[j + 2] = t.z; b[j + 3] = t.w;
            }
            #pragma unroll
            for (int i = 0; i < TM; ++i)
                #pragma unroll
                for (int j = 0; j < TN; ++j)
                    acc[i][j] = fmaf(a[i], b[j], acc[i][j]);
        }
        if (kt + 1 < KT) {
            __syncthreads();
            storeA(); storeB();
            __syncthreads();
        }
    }

    #pragma unroll
    for (int i = 0; i < TM; ++i) {
        int row = m0 + ty * TM + i;
        float sc = rowScale[row];
        #pragma unroll
        for (int j = 0; j < TN; j += 4) {
            int col = n0 + tx * TN + j;
            float x0 = acc[i][j + 0] * sc;
            float x1 = acc[i][j + 1] * sc;
            float x2 = acc[i][j + 2] * sc;
            float x3 = acc[i][j + 3] * sc;
            uint2 h, l;
            h.x = packbf2(x0, x1);
            h.y = packbf2(x2, x3);
            l.x = packbf2(x0 - bf16of(x0), x1 - bf16of(x1));
            l.y = packbf2(x2 - bf16of(x2), x3 - bf16of(x3));
            size_t off = ((size_t)row * N + col) / 4;
            reinterpret_cast<uint2*>(Ch)[off] = h;
            reinterpret_cast<uint2*>(Cl)[off] = l;
            if (Cf) {
                *reinterpret_cast<float4*>(Cf + (size_t)row * N + col) =
                    make_float4(x0, x1, x2, x3);
            }
        }
    }
}

// ---------------------------------------------------------------------------
// decode: bucket sort by src (packed int2 records), block-per-src decode
// ---------------------------------------------------------------------------
__global__ void hist_kernel(const int* __restrict__ eli, int nPred)
{
    int i = blockIdx.x * blockDim.x + threadIdx.x;
    int base = i * 4;
    if (base + 3 < nPred) {
        int4 v = *reinterpret_cast<const int4*>(eli + base);
        atomicAdd(&g_cnt[v.x], 1);
        atomicAdd(&g_cnt[v.y], 1);
        atomicAdd(&g_cnt[v.z], 1);
        atomicAdd(&g_cnt[v.w], 1);
    } else {
        for (int j = base; j < nPred; ++j) atomicAdd(&g_cnt[eli[j]], 1);
    }
}

__global__ __launch_bounds__(1024)
void scan_kernel()
{
    __shared__ int part[1024];
    const int tid = threadIdx.x;
    int loc[8];
    int s = 0;
    #pragma unroll
    for (int j = 0; j < 8; ++j) {
        loc[j] = g_cnt[tid * 8 + j];
        s += loc[j];
    }
    part[tid] = s;
    __syncthreads();
    for (int off = 1; off < 1024; off <<= 1) {
        int v = (tid >= off) ? part[tid - off] : 0;
        __syncthreads();
        part[tid] += v;
        __syncthreads();
    }
    int run = part[tid] - s;      // exclusive prefix
    #pragma unroll
    for (int j = 0; j < 8; ++j) {
        g_start[tid * 8 + j] = run;
        g_cur[tid * 8 + j]   = run;
        run += loc[j];
    }
    if (tid == 1023) g_start[N_NODES] = run;
}

__global__ void scatter_kernel(const int* __restrict__ eli, int nPred)
{
    int i = blockIdx.x * blockDim.x + threadIdx.x;
    if (i >= nPred) return;
    int s = eli[i];
    int pos = atomicAdd(&g_cur[s], 1);
    g_sde[pos] = make_int2(eli[nPred + i], i);
}

__global__ __launch_bounds__(256)
void decode_sorted_kernel(float* __restrict__ out)
{
    __shared__ float zsrc[OUT_C];
    const int b   = blockIdx.x;               // src node
    const int tid = threadIdx.x;
    if (tid < OUT_C) zsrc[tid] = g_Z[(size_t)b * OUT_C + tid];
    __syncthreads();
    const int s0 = g_start[b];
    const int s1 = g_start[b + 1];
    const int lane = tid & 31;
    const int w    = tid >> 5;
    const float4 av = reinterpret_cast<const float4*>(zsrc)[lane];
    for (int e = s0 + w; e < s1; e += 8) {
        int2 de = g_sde[e];
        float4 bv = reinterpret_cast<const float4*>(g_Z + (size_t)de.x * OUT_C)[lane];
        float dot = av.x * bv.x + av.y * bv.y + av.z * bv.z + av.w * bv.w;
        #pragma unroll
        for (int o = 16; o; o >>= 1) dot += __shfl_xor_sync(0xffffffffu, dot, o);
        if (lane == 0) out[de.y] = dot;
    }
}

// ---------------------------------------------------------------------------
extern "C" void kernel_launch(void* const* d_in, const int* in_sizes, int n_in,
                              void* d_out, int out_size)
{
    const int*   nodeIdx = (const int*)  d_in[0];
    const float* attn    = (const float*)d_in[1];
    const int*   eli     = (const int*)  d_in[2];
    const float* emb     = (const float*)d_in[3];
    const float* W1      = (const float*)d_in[4];
    const float* b1      = (const float*)d_in[5];
    const float* W2      = (const float*)d_in[6];
    const float* b2      = (const float*)d_in[7];
    float* out = (float*)d_out;
    const int nPred = in_sizes[2] / 2;

    float *pDis, *pH, *pZ, *pPart;
    __nv_bfloat16 *pAh, *pAl, *pBh, *pBl;
    int* pCnt;
    cudaGetSymbolAddress((void**)&pDis,  g_dis);
    cudaGetSymbolAddress((void**)&pH,    g_H);
    cudaGetSymbolAddress((void**)&pZ,    g_Z);
    cudaGetSymbolAddress((void**)&pPart, g_part);
    cudaGetSymbolAddress((void**)&pAh,   g_Ah);
    cudaGetSymbolAddress((void**)&pAl,   g_Al);
    cudaGetSymbolAddress((void**)&pBh,   g_Bh);
    cudaGetSymbolAddress((void**)&pBl,   g_Bl);
    cudaGetSymbolAddress((void**)&pCnt,  g_cnt);

    constexpr int TC_SMEM = 3 * 4 * 32 * 136 * 2;   // 3 stages x 4 planes = 104448 B
    cudaFuncSetAttribute(tc_gemm<2>, cudaFuncAttributeMaxDynamicSharedMemorySize, TC_SMEM);
    cudaFuncSetAttribute(tc_gemm<4>, cudaFuncAttributeMaxDynamicSharedMemorySize, TC_SMEM);

    // 0) edge bucket sort
    cudaMemsetAsync(pCnt, 0, N_NODES * sizeof(int));
    hist_kernel<<<(nPred / 4 + 255) / 256, 256>>>(eli, nPred);
    scan_kernel<<<1, 1024>>>();
    scatter_kernel<<<(nPred + 255) / 256, 256>>>(eli, nPred);

    // 1) convert + deg (fused), then dis
    convert_deg_kernel<<<dim3(8, 64), 256>>>(attn);
    dis_kernel<<<N_NODES / 256, 256>>>();

    // 2) P (bf16 hi/lo) = dis ⊙ (emb[nodeIdx] @ W1)
    simt_gemm<128, 64, 16, 8, 8, true>
        <<<dim3(HID_C / 64, N_NODES / 128), 128>>>(
            emb, E_DIM_C, W1, pBh, pBl, nullptr, pDis, nodeIdx, N_NODES, HID_C, E_DIM_C);

    // 3) H partials = w^T @ P   split-K=2 (TC)
    tc_gemm<2><<<dim3(HID_C / 128, N_NODES / 128, 2), 256, TC_SMEM>>>(
        pAh, pAl, pBh, pBl, pPart, N_NODES, HID_C, N_NODES);
    reduce_epi_kernel<2, true>
        <<<(N_NODES * HID_C / 4 + 255) / 256, 256>>>(pPart, b1, pH, HID_C);

    // 4) Q (bf16 hi/lo) = dis ⊙ (H @ W2)
    simt_gemm<128, 64, 16, 8, 8, false>
        <<<dim3(OUT_C / 64, N_NODES / 128), 128>>>(
            pH, HID_C, W2, pBh, pBl, nullptr, pDis, nullptr, N_NODES, OUT_C, HID_C);

    // 5) Z partials = w^T @ Q   split-K=4 (TC)
    tc_gemm<4><<<dim3(OUT_C / 128, N_NODES / 128, 4), 256, TC_SMEM>>>(
        pAh, pAl, pBh, pBl, pPart, N_NODES, OUT_C, N_NODES);
    reduce_epi_kernel<4, false>
        <<<(N_NODES * OUT_C / 4 + 255) / 256, 256>>>(pPart, b2, pZ, OUT_C);

    // 6) decode
    decode_sorted_kernel<<<N_NODES, 256>>>(out);
}

// round 11
// speedup vs baseline: 1.2183x; 1.2183x over previous
#include <cuda_runtime.h>
#include <cuda_fp16.h>
#include <cstdint>

// ---------------------------------------------------------------------------
// Round 10: asymmetric fp16 TC GEMMs.
//   A (relu(attn)) -> ONE fp16 plane (error 2^-11, RMS ~2.8e-4/stage)
//   B (P / Q)      -> fp16 hi/lo pair, scaled by 2^14 (avoids subnormals)
//   C = A^T·(Bh+Bl) via 2 MMAs; 2^-14 folded into reduce epilogue.
//   w = relu(attn);  A_norm^T @ Y == dis ⊙ ( w^T @ (dis ⊙ Y) )
//   convert: Af = fp16(relu(attn)) + deg partials (fused)
//   P  = dis ⊙ (emb[node_idx] @ W1)        (SIMT fp32 -> fp16 hi/lo ×2^14)
//   H  = relu(dis/2^14 ⊙ Σ(w^T @ P') + b1) (TC split-K=2 + reduce)
//   Q  = dis ⊙ (H @ W2)                    (SIMT fp32 -> fp16 hi/lo ×2^14)
//   Z  = dis/2^14 ⊙ Σ(w^T @ Q') + b2      (TC split-K=4 + reduce)
//   decode: bucket-sort edges by src (packed int2), smem-cached z[src]
// ---------------------------------------------------------------------------

static constexpr int N_NODES = 8192;
static constexpr int E_DIM_C = 256;
static constexpr int HID_C   = 256;
static constexpr int OUT_C   = 128;
static constexpr int MAX_PRED = 2100000;
static constexpr float B_SCALE     = 16384.0f;       // 2^14
static constexpr float B_INV_SCALE = 1.0f / 16384.0f;

__device__ float   g_degp[128 * N_NODES];
__device__ float   g_dis [N_NODES];
__device__ __half  g_Af  [(size_t)N_NODES * N_NODES];   // 128 MB, fp16 relu(attn)
__device__ __half  g_Bh  [N_NODES * HID_C];             // P/Q hi (scaled)
__device__ __half  g_Bl  [N_NODES * HID_C];             // P/Q lo (scaled)
__device__ float   g_H   [N_NODES * HID_C];
__device__ float   g_Z   [N_NODES * OUT_C];
__device__ float   g_part[2 * N_NODES * HID_C];
// decode sort scratch
__device__ int     g_cnt  [N_NODES];
__device__ int     g_start[N_NODES + 1];
__device__ int     g_cur  [N_NODES];
__device__ int2    g_sde  [MAX_PRED];                   // .x = dst, .y = eid

// ---------------------------------------------------------------------------
// Fused convert + deg: read attn once; write relu'd fp16; col partials.
// grid (8, 128), 256 threads; thread handles 4 cols x 64 rows.
// ---------------------------------------------------------------------------
__global__ void convert_deg_kernel(const float* __restrict__ attn)
{
    int c4 = blockIdx.x * blockDim.x + threadIdx.x;   // float4 col index
    int r0 = blockIdx.y * 64;
    float4 s = make_float4(0.f, 0.f, 0.f, 0.f);
    const float4* a = reinterpret_cast<const float4*>(attn);
    #pragma unroll 4
    for (int r = 0; r < 64; ++r) {
        size_t row = r0 + r;
        float4 v = a[row * (N_NODES / 4) + c4];
        v.x = fmaxf(v.x, 0.f); v.y = fmaxf(v.y, 0.f);
        v.z = fmaxf(v.z, 0.f); v.w = fmaxf(v.w, 0.f);
        s.x += v.x; s.y += v.y; s.z += v.z; s.w += v.w;
        __half2 h0 = __floats2half2_rn(v.x, v.y);
        __half2 h1 = __floats2half2_rn(v.z, v.w);
        uint2 packed;
        packed.x = *reinterpret_cast<uint32_t*>(&h0);
        packed.y = *reinterpret_cast<uint32_t*>(&h1);
        reinterpret_cast<uint2*>(g_Af)[(row * N_NODES) / 4 + c4] = packed;
    }
    reinterpret_cast<float4*>(g_degp)[blockIdx.y * (N_NODES / 4) + c4] = s;
}

__global__ void dis_kernel()
{
    int col = blockIdx.x * blockDim.x + threadIdx.x;
    float s = 0.f;
    #pragma unroll
    for (int r = 0; r < 128; ++r) s += g_degp[(size_t)r * N_NODES + col];
    g_dis[col] = (s > 0.f) ? rsqrtf(s) : 0.f;
}

// ---------------------------------------------------------------------------
__device__ __forceinline__ void ldsm_x4_t(uint32_t& r0, uint32_t& r1,
                                          uint32_t& r2, uint32_t& r3, uint32_t addr)
{
    asm volatile("ldmatrix.sync.aligned.m8n8.x4.trans.shared.b16 {%0,%1,%2,%3}, [%4];"
                 : "=r"(r0), "=r"(r1), "=r"(r2), "=r"(r3) : "r"(addr));
}

__device__ __forceinline__ void mma16816h(float* d, const uint32_t* a, const uint32_t* b)
{
    asm volatile("mma.sync.aligned.m16n8k16.row.col.f32.f16.f16.f32 "
                 "{%0,%1,%2,%3}, {%4,%5,%6,%7}, {%8,%9}, {%0,%1,%2,%3};"
                 : "+f"(d[0]), "+f"(d[1]), "+f"(d[2]), "+f"(d[3])
                 : "r"(a[0]), "r"(a[1]), "r"(a[2]), "r"(a[3]), "r"(b[0]), "r"(b[1]));
}

__device__ __forceinline__ void cpasync16(uint32_t smem, const void* gmem)
{
    asm volatile("cp.async.cg.shared.global [%0], [%1], 16;" :: "r"(smem), "l"(gmem));
}

// ---------------------------------------------------------------------------
// TC GEMM:  Cpart[z] = Af^T(ish) @ (Bh + Bl)   (2 MMAs per k16 step)
//   Af: [K, M] fp16 row-major, Bh/Bl: [K, N] fp16 row-major (pre-scaled 2^14).
// BM=128, BN=128, BK=32, 256 threads, warp tile 64x32; 3-stage cp.async,
// 3 planes per stage, 2 CTAs/SM.
// ---------------------------------------------------------------------------
template<int SPLITK>
__global__ __launch_bounds__(256, 2)
void tc_gemm(const __half* __restrict__ Afg,
             const __half* __restrict__ Bhg,
             const __half* __restrict__ Blg,
             float* __restrict__ Cpart, int M, int N, int K)
{
    constexpr int BM = 128, BN = 128, BK = 32;
    constexpr int AP = 136;
    constexpr int STG = BK * AP;          // fp16 elems per plane per stage
    constexpr int NSTAGE = 3;

    extern __shared__ __half smheap[];
    auto plane = [&](int s, int p) { return smheap + (s * 3 + p) * STG; };

    const int tid  = threadIdx.x;
    const int lane = tid & 31;
    const int wid  = tid >> 5;
    const int wm   = (wid >> 2) * 64;
    const int wn   = (wid & 3) * 32;
    const int m0   = blockIdx.y * BM;
    const int n0   = blockIdx.x * BN;
    const int Ksp  = K / SPLITK;
    const int kB   = blockIdx.z * Ksp;
    const int KT   = Ksp / BK;

    float acc[4][4][4];
    #pragma unroll
    for (int i = 0; i < 4; ++i)
        #pragma unroll
        for (int j = 0; j < 4; ++j)
            #pragma unroll
            for (int q = 0; q < 4; ++q) acc[i][j][q] = 0.f;

    auto issue = [&](int kt, int s) {
        int kg = kB + kt * BK;
        uint32_t base = (uint32_t)__cvta_generic_to_shared(plane(s, 0));
        #pragma unroll
        for (int v = 0; v < 2; ++v) {
            int idx  = tid + v * 256;
            int row  = idx >> 4;            // 0..31
            int c16  = idx & 15;            // 16B chunk
            uint32_t so = row * (AP * 2) + c16 * 16;
            size_t   aoff = (size_t)(kg + row) * M + m0 + c16 * 8;
            size_t   boff = (size_t)(kg + row) * N + n0 + c16 * 8;
            cpasync16(base + 0 * STG * 2 + so, Afg + aoff);
            cpasync16(base + 1 * STG * 2 + so, Bhg + boff);
            cpasync16(base + 2 * STG * 2 + so, Blg + boff);
        }
        asm volatile("cp.async.commit_group;");
    };

    const int aRow = (lane & 7) + ((lane >> 4) & 1) * 8;
    const int aCol = wm + ((lane >> 3) & 1) * 8;
    const int bRow = (lane & 7) + ((lane >> 3) & 1) * 8;
    const int bCol = wn + ((lane >> 4) & 1) * 8;

    auto compute = [&](int s) {
        uint32_t afB = (uint32_t)__cvta_generic_to_shared(plane(s, 0));
        uint32_t bhB = (uint32_t)__cvta_generic_to_shared(plane(s, 1));
        uint32_t blB = (uint32_t)__cvta_generic_to_shared(plane(s, 2));
        #pragma unroll
        for (int k16 = 0; k16 < 2; ++k16) {
            int k0 = k16 * 16;
            uint32_t bhf[4][2], blf[4][2];
            #pragma unroll
            for (int p = 0; p < 2; ++p) {
                uint32_t off = ((k0 + bRow) * AP + bCol + p * 16) * 2;
                uint32_t r0, r1, r2, r3;
                ldsm_x4_t(r0, r1, r2, r3, bhB + off);
                bhf[2 * p][0] = r0; bhf[2 * p][1] = r1;
                bhf[2 * p + 1][0] = r2; bhf[2 * p + 1][1] = r3;
                ldsm_x4_t(r0, r1, r2, r3, blB + off);
                blf[2 * p][0] = r0; blf[2 * p][1] = r1;
                blf[2 * p + 1][0] = r2; blf[2 * p + 1][1] = r3;
            }
            #pragma unroll
            for (int mi = 0; mi < 4; ++mi) {
                uint32_t af[4];
                uint32_t off = ((k0 + aRow) * AP + aCol + mi * 16) * 2;
                ldsm_x4_t(af[0], af[1], af[2], af[3], afB + off);
                #pragma unroll
                for (int ni = 0; ni < 4; ++ni) {
                    mma16816h(acc[mi][ni], af, bhf[ni]);
                    mma16816h(acc[mi][ni], af, blf[ni]);
                }
            }
        }
    };

    // prologue: fill pipeline
    issue(0, 0);
    if (KT > 1) issue(1, 1);
    if (KT > 2) issue(2, 2);

    for (int kt = 0; kt < KT; ++kt) {
        asm volatile("cp.async.wait_group %0;" :: "n"(NSTAGE - 2));
        __syncthreads();
        compute(kt % NSTAGE);
        __syncthreads();
        if (kt + NSTAGE < KT) {
            issue(kt + NSTAGE, kt % NSTAGE);
        } else if (kt + 1 < KT) {
            asm volatile("cp.async.commit_group;");   // keep group accounting aligned
        }
    }

    float* Cp = Cpart + (size_t)blockIdx.z * M * N;
    const int rB = m0 + wm + (lane >> 2);
    const int cB = n0 + wn + (lane & 3) * 2;
    #pragma unroll
    for (int mi = 0; mi < 4; ++mi)
        #pragma unroll
        for (int ni = 0; ni < 4; ++ni) {
            int r = rB + mi * 16;
            int c = cB + ni * 8;
            *reinterpret_cast<float2*>(Cp + (size_t)r * N + c) =
                make_float2(acc[mi][ni][0], acc[mi][ni][1]);
            *reinterpret_cast<float2*>(Cp + (size_t)(r + 8) * N + c) =
                make_float2(acc[mi][ni][2], acc[mi][ni][3]);
        }
}

// ---------------------------------------------------------------------------
// reduce split-K partials + epilogue; folds the 2^-14 B-plane scale into sc.
// ---------------------------------------------------------------------------
template<int SPLITK, bool RELU>
__global__ void reduce_epi_kernel(const float* __restrict__ part,
                                  const float* __restrict__ bias,
                                  float* __restrict__ C, int N)
{
    int i4 = blockIdx.x * blockDim.x + threadIdx.x;
    int MN4 = N_NODES * N / 4;
    if (i4 >= MN4) return;
    const float4* p = reinterpret_cast<const float4*>(part);
    float4 s = p[i4];
    #pragma unroll
    for (int sp = 1; sp < SPLITK; ++sp) {
        float4 v = p[i4 + (size_t)sp * MN4];
        s.x += v.x; s.y += v.y; s.z += v.z; s.w += v.w;
    }
    int row = (i4 * 4) / N;
    int col = (i4 * 4) % N;
    float sc = g_dis[row] * B_INV_SCALE;
    float4 bb = *reinterpret_cast<const float4*>(bias + col);
    float4 r;
    r.x = s.x * sc + bb.x;
    r.y = s.y * sc + bb.y;
    r.z = s.z * sc + bb.z;
    r.w = s.w * sc + bb.w;
    if (RELU) {
        r.x = fmaxf(r.x, 0.f); r.y = fmaxf(r.y, 0.f);
        r.z = fmaxf(r.z, 0.f); r.w = fmaxf(r.w, 0.f);
    }
    reinterpret_cast<float4*>(C)[i4] = r;
}

// ---------------------------------------------------------------------------
// SIMT fp32 GEMM; epilogue writes scaled fp16 hi/lo planes (+ optional fp32).
// ---------------------------------------------------------------------------
template<int BM, int BN, int BK, int TM, int TN, bool GATHER_A>
__global__ __launch_bounds__((BM / TM) * (BN / TN))
void simt_gemm(const float* __restrict__ A, int lda,
               const float* __restrict__ B,
               __half* __restrict__ Ch,
               __half* __restrict__ Cl,
               const float* __restrict__ rowScale,
               const int* __restrict__ gatherIdx,
               int M, int N, int K)
{
    constexpr int NT   = (BM / TM) * (BN / TN);
    constexpr int APAD = 4;
    constexpr int AV   = (BM * BK) / (4 * NT);
    constexpr int BV   = (BK * BN) / (4 * NT);

    __shared__ float As[BK][BM + APAD];
    __shared__ float Bs[BK][BN];

    const int tid = threadIdx.x;
    const int tx  = tid % (BN / TN);
    const int ty  = tid / (BN / TN);
    const int m0  = blockIdx.y * BM;
    const int n0  = blockIdx.x * BN;

    float4 areg[AV], breg[BV];
    float acc[TM][TN];
    #pragma unroll
    for (int i = 0; i < TM; ++i)
        #pragma unroll
        for (int j = 0; j < TN; ++j) acc[i][j] = 0.f;

    auto loadA = [&](int k0) {
        #pragma unroll
        for (int v = 0; v < AV; ++v) {
            int idx = tid + v * NT;
            int m  = idx / (BK / 4);
            int kq = idx % (BK / 4);
            int row = GATHER_A ? gatherIdx[m0 + m] : (m0 + m);
            areg[v] = *reinterpret_cast<const float4*>(A + (size_t)row * lda + (k0 + kq * 4));
        }
    };
    auto storeA = [&]() {
        #pragma unroll
        for (int v = 0; v < AV; ++v) {
            int idx = tid + v * NT;
            int m  = idx / (BK / 4);
            int kq = idx % (BK / 4);
            As[kq * 4 + 0][m] = areg[v].x;
            As[kq * 4 + 1][m] = areg[v].y;
            As[kq * 4 + 2][m] = areg[v].z;
            As[kq * 4 + 3][m] = areg[v].w;
        }
    };
    auto loadB = [&](int k0) {
        #pragma unroll
        for (int v = 0; v < BV; ++v) {
            int idx = tid + v * NT;
            int k  = idx / (BN / 4);
            int n4 = idx % (BN / 4);
            breg[v] = *reinterpret_cast<const float4*>(B + (size_t)(k0 + k) * N + (n0 + n4 * 4));
        }
    };
    auto storeB = [&]() {
        #pragma unroll
        for (int v = 0; v < BV; ++v) {
            int idx = tid + v * NT;
            int k  = idx / (BN / 4);
            int n4 = idx % (BN / 4);
            *reinterpret_cast<float4*>(&Bs[k][n4 * 4]) = breg[v];
        }
    };

    loadA(0); loadB(0);
    storeA(); storeB();
    __syncthreads();

    const int KT = K / BK;
    for (int kt = 0; kt < KT; ++kt) {
        if (kt + 1 < KT) { loadA((kt + 1) * BK); loadB((kt + 1) * BK); }
        #pragma unroll
        for (int kk = 0; kk < BK; ++kk) {
            float a[TM], b[TN];
            #pragma unroll
            for (int i = 0; i < TM; i += 4) {
                float4 t = *reinterpret_cast<const float4*>(&As[kk][ty * TM + i]);
                a[i] = t.x; a[i + 1] = t.y; a[i + 2] = t.z; a[i + 3] = t.w;
            }
            #pragma unroll
            for (int j = 0; j < TN; j += 4) {
                float4 t = *reinterpret_cast<const float4*>(&Bs[kk][tx * TN + j]);
                b[j] = t.x; b[j + 1] = t.y; b[j + 2] = t.z; b[j + 3] = t.w;
            }
            #pragma unroll
            for (int i = 0; i < TM; ++i)
                #pragma unroll
                for (int j = 0; j < TN; ++j)
                    acc[i][j] = fmaf(a[i], b[j], acc[i][j]);
        }
        if (kt + 1 < KT) {
            __syncthreads();
            storeA(); storeB();
            __syncthreads();
        }
    }

    #pragma unroll
    for (int i = 0; i < TM; ++i) {
        int row = m0 + ty * TM + i;
        float sc = rowScale[row];
        #pragma unroll
        for (int j = 0; j < TN; j += 4) {
            int col = n0 + tx * TN + j;
            float x[4];
            x[0] = acc[i][j + 0] * sc;
            x[1] = acc[i][j + 1] * sc;
            x[2] = acc[i][j + 2] * sc;
            x[3] = acc[i][j + 3] * sc;
            __half h[4], l[4];
            #pragma unroll
            for (int q = 0; q < 4; ++q) {
                float xs = x[q] * B_SCALE;
                h[q] = __float2half_rn(xs);
                l[q] = __float2half_rn(xs - __half2float(h[q]));
            }
            size_t off = ((size_t)row * N + col) / 4;
            reinterpret_cast<uint2*>(Ch)[off] = *reinterpret_cast<uint2*>(h);
            reinterpret_cast<uint2*>(Cl)[off] = *reinterpret_cast<uint2*>(l);
        }
    }
}

// ---------------------------------------------------------------------------
// decode: bucket sort by src (packed int2 records), block-per-src decode
// ---------------------------------------------------------------------------
__global__ void hist_kernel(const int* __restrict__ eli, int nPred)
{
    int i = blockIdx.x * blockDim.x + threadIdx.x;
    int base = i * 4;
    if (base + 3 < nPred) {
        int4 v = *reinterpret_cast<const int4*>(eli + base);
        atomicAdd(&g_cnt[v.x], 1);
        atomicAdd(&g_cnt[v.y], 1);
        atomicAdd(&g_cnt[v.z], 1);
        atomicAdd(&g_cnt[v.w], 1);
    } else {
        for (int j = base; j < nPred; ++j) atomicAdd(&g_cnt[eli[j]], 1);
    }
}

__global__ __launch_bounds__(1024)
void scan_kernel()
{
    __shared__ int part[1024];
    const int tid = threadIdx.x;
    int loc[8];
    int s = 0;
    #pragma unroll
    for (int j = 0; j < 8; ++j) {
        loc[j] = g_cnt[tid * 8 + j];
        s += loc[j];
    }
    part[tid] = s;
    __syncthreads();
    for (int off = 1; off < 1024; off <<= 1) {
        int v = (tid >= off) ? part[tid - off] : 0;
        __syncthreads();
        part[tid] += v;
        __syncthreads();
    }
    int run = part[tid] - s;      // exclusive prefix
    #pragma unroll
    for (int j = 0; j < 8; ++j) {
        g_start[tid * 8 + j] = run;
        g_cur[tid * 8 + j]   = run;
        run += loc[j];
    }
    if (tid == 1023) g_start[N_NODES] = run;
}

__global__ void scatter_kernel(const int* __restrict__ eli, int nPred)
{
    int i = blockIdx.x * blockDim.x + threadIdx.x;
    if (i >= nPred) return;
    int s = eli[i];
    int pos = atomicAdd(&g_cur[s], 1);
    g_sde[pos] = make_int2(eli[nPred + i], i);
}

__global__ __launch_bounds__(256)
void decode_sorted_kernel(float* __restrict__ out)
{
    __shared__ float zsrc[OUT_C];
    const int b   = blockIdx.x;               // src node
    const int tid = threadIdx.x;
    if (tid < OUT_C) zsrc[tid] = g_Z[(size_t)b * OUT_C + tid];
    __syncthreads();
    const int s0 = g_start[b];
    const int s1 = g_start[b + 1];
    const int lane = tid & 31;
    const int w    = tid >> 5;
    const float4 av = reinterpret_cast<const float4*>(zsrc)[lane];
    for (int e = s0 + w; e < s1; e += 8) {
        int2 de = g_sde[e];
        float4 bv = reinterpret_cast<const float4*>(g_Z + (size_t)de.x * OUT_C)[lane];
        float dot = av.x * bv.x + av.y * bv.y + av.z * bv.z + av.w * bv.w;
        #pragma unroll
        for (int o = 16; o; o >>= 1) dot += __shfl_xor_sync(0xffffffffu, dot, o);
        if (lane == 0) out[de.y] = dot;
    }
}

// ---------------------------------------------------------------------------
extern "C" void kernel_launch(void* const* d_in, const int* in_sizes, int n_in,
                              void* d_out, int out_size)
{
    const int*   nodeIdx = (const int*)  d_in[0];
    const float* attn    = (const float*)d_in[1];
    const int*   eli     = (const int*)  d_in[2];
    const float* emb     = (const float*)d_in[3];
    const float* W1      = (const float*)d_in[4];
    const float* b1      = (const float*)d_in[5];
    const float* W2      = (const float*)d_in[6];
    const float* b2      = (const float*)d_in[7];
    float* out = (float*)d_out;
    const int nPred = in_sizes[2] / 2;

    float *pDis, *pH, *pZ, *pPart;
    __half *pAf, *pBh, *pBl;
    int* pCnt;
    cudaGetSymbolAddress((void**)&pDis,  g_dis);
    cudaGetSymbolAddress((void**)&pH,    g_H);
    cudaGetSymbolAddress((void**)&pZ,    g_Z);
    cudaGetSymbolAddress((void**)&pPart, g_part);
    cudaGetSymbolAddress((void**)&pAf,   g_Af);
    cudaGetSymbolAddress((void**)&pBh,   g_Bh);
    cudaGetSymbolAddress((void**)&pBl,   g_Bl);
    cudaGetSymbolAddress((void**)&pCnt,  g_cnt);

    constexpr int TC_SMEM = 3 * 3 * 32 * 136 * 2;   // 3 stages x 3 planes = 78336 B
    cudaFuncSetAttribute(tc_gemm<2>, cudaFuncAttributeMaxDynamicSharedMemorySize, TC_SMEM);
    cudaFuncSetAttribute(tc_gemm<4>, cudaFuncAttributeMaxDynamicSharedMemorySize, TC_SMEM);

    // 0) edge bucket sort
    cudaMemsetAsync(pCnt, 0, N_NODES * sizeof(int));
    hist_kernel<<<(nPred / 4 + 255) / 256, 256>>>(eli, nPred);
    scan_kernel<<<1, 1024>>>();
    scatter_kernel<<<(nPred + 255) / 256, 256>>>(eli, nPred);

    // 1) convert + deg (fused), then dis
    convert_deg_kernel<<<dim3(8, 128), 256>>>(attn);
    dis_kernel<<<N_NODES / 256, 256>>>();

    // 2) P (fp16 hi/lo x 2^14) = dis ⊙ (emb[nodeIdx] @ W1)
    simt_gemm<128, 64, 16, 8, 8, true>
        <<<dim3(HID_C / 64, N_NODES / 128), 128>>>(
            emb, E_DIM_C, W1, pBh, pBl, pDis, nodeIdx, N_NODES, HID_C, E_DIM_C);

    // 3) H partials = w^T @ P'   split-K=2 (TC, 2-MMA fp16)
    tc_gemm<2><<<dim3(HID_C / 128, N_NODES / 128, 2), 256, TC_SMEM>>>(
        pAf, pBh, pBl, pPart, N_NODES, HID_C, N_NODES);
    reduce_epi_kernel<2, true>
        <<<(N_NODES * HID_C / 4 + 255) / 256, 256>>>(pPart, b1, pH, HID_C);

    // 4) Q (fp16 hi/lo x 2^14) = dis ⊙ (H @ W2)
    simt_gemm<128, 64, 16, 8, 8, false>
        <<<dim3(OUT_C / 64, N_NODES / 128), 128>>>(
            pH, HID_C, W2, pBh, pBl, pDis, nullptr, N_NODES, OUT_C, HID_C);

    // 5) Z partials = w^T @ Q'   split-K=4 (TC, 2-MMA fp16)
    tc_gemm<4><<<dim3(OUT_C / 128, N_NODES / 128, 4), 256, TC_SMEM>>>(
        pAf, pBh, pBl, pPart, N_NODES, OUT_C, N_NODES);
    reduce_epi_kernel<4, false>
        <<<(N_NODES * OUT_C / 4 + 255) / 256, 256>>>(pPart, b2, pZ, OUT_C);

    // 6) decode
    decode_sorted_kernel<<<N_NODES, 256>>>(out);
}

// round 12
// speedup vs baseline: 1.5372x; 1.2618x over previous
#include <cuda_runtime.h>
#include <cuda_fp16.h>
#include <cstdint>

// ---------------------------------------------------------------------------
// Round 11: pure-fp16 TC GEMMs (1 MMA per k16 step).
//   A (relu(attn)) -> fp16 plane;  B (P/Q) -> ONE fp16 plane, scaled 2^14.
//   Error budget: A and B each contribute ~2^-11 relative rounding which
//   averages over K=8192 -> measured-scale rel_err ~5e-5, gate is 1e-3.
//   w = relu(attn);  A_norm^T @ Y == dis ⊙ ( w^T @ (dis ⊙ Y) )
//   convert: Af = fp16(relu(attn)) + deg partials (fused)
//   P  = dis ⊙ (emb[node_idx] @ W1)        (SIMT fp32 -> fp16 ×2^14)
//   H  = relu(dis/2^14 ⊙ Σ(w^T @ P') + b1) (TC split-K=2 + reduce)
//   Q  = dis ⊙ (H @ W2)                    (SIMT fp32 -> fp16 ×2^14)
//   Z  = dis/2^14 ⊙ Σ(w^T @ Q') + b2      (TC split-K=4 + reduce)
//   decode: bucket-sort edges by src (packed int2), smem-cached z[src]
// ---------------------------------------------------------------------------

static constexpr int N_NODES = 8192;
static constexpr int E_DIM_C = 256;
static constexpr int HID_C   = 256;
static constexpr int OUT_C   = 128;
static constexpr int MAX_PRED = 2100000;
static constexpr float B_SCALE     = 16384.0f;       // 2^14
static constexpr float B_INV_SCALE = 1.0f / 16384.0f;

__device__ float   g_degp[128 * N_NODES];
__device__ float   g_dis [N_NODES];
__device__ __half  g_Af  [(size_t)N_NODES * N_NODES];   // 128 MB fp16 relu(attn)
__device__ __half  g_Bf  [N_NODES * HID_C];             // P/Q (scaled fp16)
__device__ float   g_H   [N_NODES * HID_C];
__device__ float   g_Z   [N_NODES * OUT_C];
__device__ float   g_part[2 * N_NODES * HID_C];
// decode sort scratch
__device__ int     g_cnt  [N_NODES];
__device__ int     g_start[N_NODES + 1];
__device__ int     g_cur  [N_NODES];
__device__ int2    g_sde  [MAX_PRED];                   // .x = dst, .y = eid

// ---------------------------------------------------------------------------
// Fused convert + deg: read attn once; write relu'd fp16; col partials.
// ---------------------------------------------------------------------------
__global__ void convert_deg_kernel(const float* __restrict__ attn)
{
    int c4 = blockIdx.x * blockDim.x + threadIdx.x;
    int r0 = blockIdx.y * 64;
    float4 s = make_float4(0.f, 0.f, 0.f, 0.f);
    const float4* a = reinterpret_cast<const float4*>(attn);
    #pragma unroll 4
    for (int r = 0; r < 64; ++r) {
        size_t row = r0 + r;
        float4 v = a[row * (N_NODES / 4) + c4];
        v.x = fmaxf(v.x, 0.f); v.y = fmaxf(v.y, 0.f);
        v.z = fmaxf(v.z, 0.f); v.w = fmaxf(v.w, 0.f);
        s.x += v.x; s.y += v.y; s.z += v.z; s.w += v.w;
        __half2 h0 = __floats2half2_rn(v.x, v.y);
        __half2 h1 = __floats2half2_rn(v.z, v.w);
        uint2 packed;
        packed.x = *reinterpret_cast<uint32_t*>(&h0);
        packed.y = *reinterpret_cast<uint32_t*>(&h1);
        reinterpret_cast<uint2*>(g_Af)[(row * N_NODES) / 4 + c4] = packed;
    }
    reinterpret_cast<float4*>(g_degp)[blockIdx.y * (N_NODES / 4) + c4] = s;
}

__global__ void dis_kernel()
{
    int col = blockIdx.x * blockDim.x + threadIdx.x;
    float s = 0.f;
    #pragma unroll
    for (int r = 0; r < 128; ++r) s += g_degp[(size_t)r * N_NODES + col];
    g_dis[col] = (s > 0.f) ? rsqrtf(s) : 0.f;
}

// ---------------------------------------------------------------------------
__device__ __forceinline__ void ldsm_x4_t(uint32_t& r0, uint32_t& r1,
                                          uint32_t& r2, uint32_t& r3, uint32_t addr)
{
    asm volatile("ldmatrix.sync.aligned.m8n8.x4.trans.shared.b16 {%0,%1,%2,%3}, [%4];"
                 : "=r"(r0), "=r"(r1), "=r"(r2), "=r"(r3) : "r"(addr));
}

__device__ __forceinline__ void mma16816h(float* d, const uint32_t* a, const uint32_t* b)
{
    asm volatile("mma.sync.aligned.m16n8k16.row.col.f32.f16.f16.f32 "
                 "{%0,%1,%2,%3}, {%4,%5,%6,%7}, {%8,%9}, {%0,%1,%2,%3};"
                 : "+f"(d[0]), "+f"(d[1]), "+f"(d[2]), "+f"(d[3])
                 : "r"(a[0]), "r"(a[1]), "r"(a[2]), "r"(a[3]), "r"(b[0]), "r"(b[1]));
}

__device__ __forceinline__ void cpasync16(uint32_t smem, const void* gmem)
{
    asm volatile("cp.async.cg.shared.global [%0], [%1], 16;" :: "r"(smem), "l"(gmem));
}

// ---------------------------------------------------------------------------
// TC GEMM:  Cpart[z] = Af^T(ish) @ Bf   (1 MMA per k16 step per subtile)
//   Af: [K, M] fp16 row-major, Bf: [K, N] fp16 row-major (pre-scaled 2^14).
// BM=128, BN=128, BK=32, 256 threads, warp tile 64x32; 3-stage cp.async,
// 2 planes per stage (17408 B/stage), 2 CTAs/SM.
// ---------------------------------------------------------------------------
template<int SPLITK>
__global__ __launch_bounds__(256, 2)
void tc_gemm(const __half* __restrict__ Afg,
             const __half* __restrict__ Bfg,
             float* __restrict__ Cpart, int M, int N, int K)
{
    constexpr int BM = 128, BN = 128, BK = 32;
    constexpr int AP = 136;
    constexpr int STG = BK * AP;
    constexpr int NSTAGE = 3;

    extern __shared__ __half smheap[];
    auto plane = [&](int s, int p) { return smheap + (s * 2 + p) * STG; };

    const int tid  = threadIdx.x;
    const int lane = tid & 31;
    const int wid  = tid >> 5;
    const int wm   = (wid >> 2) * 64;
    const int wn   = (wid & 3) * 32;
    const int m0   = blockIdx.y * BM;
    const int n0   = blockIdx.x * BN;
    const int Ksp  = K / SPLITK;
    const int kB   = blockIdx.z * Ksp;
    const int KT   = Ksp / BK;

    float acc[4][4][4];
    #pragma unroll
    for (int i = 0; i < 4; ++i)
        #pragma unroll
        for (int j = 0; j < 4; ++j)
            #pragma unroll
            for (int q = 0; q < 4; ++q) acc[i][j][q] = 0.f;

    auto issue = [&](int kt, int s) {
        int kg = kB + kt * BK;
        uint32_t base = (uint32_t)__cvta_generic_to_shared(plane(s, 0));
        #pragma unroll
        for (int v = 0; v < 2; ++v) {
            int idx  = tid + v * 256;
            int row  = idx >> 4;
            int c16  = idx & 15;
            uint32_t so = row * (AP * 2) + c16 * 16;
            size_t   aoff = (size_t)(kg + row) * M + m0 + c16 * 8;
            size_t   boff = (size_t)(kg + row) * N + n0 + c16 * 8;
            cpasync16(base + 0 * STG * 2 + so, Afg + aoff);
            cpasync16(base + 1 * STG * 2 + so, Bfg + boff);
        }
        asm volatile("cp.async.commit_group;");
    };

    const int aRow = (lane & 7) + ((lane >> 4) & 1) * 8;
    const int aCol = wm + ((lane >> 3) & 1) * 8;
    const int bRow = (lane & 7) + ((lane >> 3) & 1) * 8;
    const int bCol = wn + ((lane >> 4) & 1) * 8;

    auto compute = [&](int s) {
        uint32_t afB = (uint32_t)__cvta_generic_to_shared(plane(s, 0));
        uint32_t bfB = (uint32_t)__cvta_generic_to_shared(plane(s, 1));
        #pragma unroll
        for (int k16 = 0; k16 < 2; ++k16) {
            int k0 = k16 * 16;
            uint32_t bf[4][2];
            #pragma unroll
            for (int p = 0; p < 2; ++p) {
                uint32_t off = ((k0 + bRow) * AP + bCol + p * 16) * 2;
                uint32_t r0, r1, r2, r3;
                ldsm_x4_t(r0, r1, r2, r3, bfB + off);
                bf[2 * p][0] = r0; bf[2 * p][1] = r1;
                bf[2 * p + 1][0] = r2; bf[2 * p + 1][1] = r3;
            }
            #pragma unroll
            for (int mi = 0; mi < 4; ++mi) {
                uint32_t af[4];
                uint32_t off = ((k0 + aRow) * AP + aCol + mi * 16) * 2;
                ldsm_x4_t(af[0], af[1], af[2], af[3], afB + off);
                #pragma unroll
                for (int ni = 0; ni < 4; ++ni)
                    mma16816h(acc[mi][ni], af, bf[ni]);
            }
        }
    };

    issue(0, 0);
    if (KT > 1) issue(1, 1);
    if (KT > 2) issue(2, 2);

    for (int kt = 0; kt < KT; ++kt) {
        asm volatile("cp.async.wait_group %0;" :: "n"(NSTAGE - 2));
        __syncthreads();
        compute(kt % NSTAGE);
        __syncthreads();
        if (kt + NSTAGE < KT) {
            issue(kt + NSTAGE, kt % NSTAGE);
        } else if (kt + 1 < KT) {
            asm volatile("cp.async.commit_group;");
        }
    }

    float* Cp = Cpart + (size_t)blockIdx.z * M * N;
    const int rB = m0 + wm + (lane >> 2);
    const int cB = n0 + wn + (lane & 3) * 2;
    #pragma unroll
    for (int mi = 0; mi < 4; ++mi)
        #pragma unroll
        for (int ni = 0; ni < 4; ++ni) {
            int r = rB + mi * 16;
            int c = cB + ni * 8;
            *reinterpret_cast<float2*>(Cp + (size_t)r * N + c) =
                make_float2(acc[mi][ni][0], acc[mi][ni][1]);
            *reinterpret_cast<float2*>(Cp + (size_t)(r + 8) * N + c) =
                make_float2(acc[mi][ni][2], acc[mi][ni][3]);
        }
}

// ---------------------------------------------------------------------------
template<int SPLITK, bool RELU>
__global__ void reduce_epi_kernel(const float* __restrict__ part,
                                  const float* __restrict__ bias,
                                  float* __restrict__ C, int N)
{
    int i4 = blockIdx.x * blockDim.x + threadIdx.x;
    int MN4 = N_NODES * N / 4;
    if (i4 >= MN4) return;
    const float4* p = reinterpret_cast<const float4*>(part);
    float4 s = p[i4];
    #pragma unroll
    for (int sp = 1; sp < SPLITK; ++sp) {
        float4 v = p[i4 + (size_t)sp * MN4];
        s.x += v.x; s.y += v.y; s.z += v.z; s.w += v.w;
    }
    int row = (i4 * 4) / N;
    int col = (i4 * 4) % N;
    float sc = g_dis[row] * B_INV_SCALE;
    float4 bb = *reinterpret_cast<const float4*>(bias + col);
    float4 r;
    r.x = s.x * sc + bb.x;
    r.y = s.y * sc + bb.y;
    r.z = s.z * sc + bb.z;
    r.w = s.w * sc + bb.w;
    if (RELU) {
        r.x = fmaxf(r.x, 0.f); r.y = fmaxf(r.y, 0.f);
        r.z = fmaxf(r.z, 0.f); r.w = fmaxf(r.w, 0.f);
    }
    reinterpret_cast<float4*>(C)[i4] = r;
}

// ---------------------------------------------------------------------------
// SIMT fp32 GEMM; epilogue writes one scaled fp16 plane.
// ---------------------------------------------------------------------------
template<int BM, int BN, int BK, int TM, int TN, bool GATHER_A>
__global__ __launch_bounds__((BM / TM) * (BN / TN))
void simt_gemm(const float* __restrict__ A, int lda,
               const float* __restrict__ B,
               __half* __restrict__ Cf,
               const float* __restrict__ rowScale,
               const int* __restrict__ gatherIdx,
               int M, int N, int K)
{
    constexpr int NT   = (BM / TM) * (BN / TN);
    constexpr int APAD = 4;
    constexpr int AV   = (BM * BK) / (4 * NT);
    constexpr int BV   = (BK * BN) / (4 * NT);

    __shared__ float As[BK][BM + APAD];
    __shared__ float Bs[BK][BN];

    const int tid = threadIdx.x;
    const int tx  = tid % (BN / TN);
    const int ty  = tid / (BN / TN);
    const int m0  = blockIdx.y * BM;
    const int n0  = blockIdx.x * BN;

    float4 areg[AV], breg[BV];
    float acc[TM][TN];
    #pragma unroll
    for (int i = 0; i < TM; ++i)
        #pragma unroll
        for (int j = 0; j < TN; ++j) acc[i][j] = 0.f;

    auto loadA = [&](int k0) {
        #pragma unroll
        for (int v = 0; v < AV; ++v) {
            int idx = tid + v * NT;
            int m  = idx / (BK / 4);
            int kq = idx % (BK / 4);
            int row = GATHER_A ? gatherIdx[m0 + m] : (m0 + m);
            areg[v] = *reinterpret_cast<const float4*>(A + (size_t)row * lda + (k0 + kq * 4));
        }
    };
    auto storeA = [&]() {
        #pragma unroll
        for (int v = 0; v < AV; ++v) {
            int idx = tid + v * NT;
            int m  = idx / (BK / 4);
            int kq = idx % (BK / 4);
            As[kq * 4 + 0][m] = areg[v].x;
            As[kq * 4 + 1][m] = areg[v].y;
            As[kq * 4 + 2][m] = areg[v].z;
            As[kq * 4 + 3][m] = areg[v].w;
        }
    };
    auto loadB = [&](int k0) {
        #pragma unroll
        for (int v = 0; v < BV; ++v) {
            int idx = tid + v * NT;
            int k  = idx / (BN / 4);
            int n4 = idx % (BN / 4);
            breg[v] = *reinterpret_cast<const float4*>(B + (size_t)(k0 + k) * N + (n0 + n4 * 4));
        }
    };
    auto storeB = [&]() {
        #pragma unroll
        for (int v = 0; v < BV; ++v) {
            int idx = tid + v * NT;
            int k  = idx / (BN / 4);
            int n4 = idx % (BN / 4);
            *reinterpret_cast<float4*>(&Bs[k][n4 * 4]) = breg[v];
        }
    };

    loadA(0); loadB(0);
    storeA(); storeB();
    __syncthreads();

    const int KT = K / BK;
    for (int kt = 0; kt < KT; ++kt) {
        if (kt + 1 < KT) { loadA((kt + 1) * BK); loadB((kt + 1) * BK); }
        #pragma unroll
        for (int kk = 0; kk < BK; ++kk) {
            float a[TM], b[TN];
            #pragma unroll
            for (int i = 0; i < TM; i += 4) {
                float4 t = *reinterpret_cast<const float4*>(&As[kk][ty * TM + i]);
                a[i] = t.x; a[i + 1] = t.y; a[i + 2] = t.z; a[i + 3] = t.w;
            }
            #pragma unroll
            for (int j = 0; j < TN; j += 4) {
                float4 t = *reinterpret_cast<const float4*>(&Bs[kk][tx * TN + j]);
                b[j] = t.x; b[j + 1] = t.y; b[j + 2] = t.z; b[j + 3] = t.w;
            }
            #pragma unroll
            for (int i = 0; i < TM; ++i)
                #pragma unroll
                for (int j = 0; j < TN; ++j)
                    acc[i][j] = fmaf(a[i], b[j], acc[i][j]);
        }
        if (kt + 1 < KT) {
            __syncthreads();
            storeA(); storeB();
            __syncthreads();
        }
    }

    #pragma unroll
    for (int i = 0; i < TM; ++i) {
        int row = m0 + ty * TM + i;
        float sc = rowScale[row] * B_SCALE;
        #pragma unroll
        for (int j = 0; j < TN; j += 4) {
            int col = n0 + tx * TN + j;
            __half h[4];
            h[0] = __float2half_rn(acc[i][j + 0] * sc);
            h[1] = __float2half_rn(acc[i][j + 1] * sc);
            h[2] = __float2half_rn(acc[i][j + 2] * sc);
            h[3] = __float2half_rn(acc[i][j + 3] * sc);
            reinterpret_cast<uint2*>(Cf)[((size_t)row * N + col) / 4] =
                *reinterpret_cast<uint2*>(h);
        }
    }
}

// ---------------------------------------------------------------------------
// decode: bucket sort by src (packed int2 records), block-per-src decode
// ---------------------------------------------------------------------------
__global__ void hist_kernel(const int* __restrict__ eli, int nPred)
{
    int i = blockIdx.x * blockDim.x + threadIdx.x;
    int base = i * 4;
    if (base + 3 < nPred) {
        int4 v = *reinterpret_cast<const int4*>(eli + base);
        atomicAdd(&g_cnt[v.x], 1);
        atomicAdd(&g_cnt[v.y], 1);
        atomicAdd(&g_cnt[v.z], 1);
        atomicAdd(&g_cnt[v.w], 1);
    } else {
        for (int j = base; j < nPred; ++j) atomicAdd(&g_cnt[eli[j]], 1);
    }
}

__global__ __launch_bounds__(1024)
void scan_kernel()
{
    __shared__ int part[1024];
    const int tid = threadIdx.x;
    int loc[8];
    int s = 0;
    #pragma unroll
    for (int j = 0; j < 8; ++j) {
        loc[j] = g_cnt[tid * 8 + j];
        s += loc[j];
    }
    part[tid] = s;
    __syncthreads();
    for (int off = 1; off < 1024; off <<= 1) {
        int v = (tid >= off) ? part[tid - off] : 0;
        __syncthreads();
        part[tid] += v;
        __syncthreads();
    }
    int run = part[tid] - s;
    #pragma unroll
    for (int j = 0; j < 8; ++j) {
        g_start[tid * 8 + j] = run;
        g_cur[tid * 8 + j]   = run;
        run += loc[j];
    }
    if (tid == 1023) g_start[N_NODES] = run;
}

__global__ void scatter_kernel(const int* __restrict__ eli, int nPred)
{
    int i = blockIdx.x * blockDim.x + threadIdx.x;
    if (i >= nPred) return;
    int s = eli[i];
    int pos = atomicAdd(&g_cur[s], 1);
    g_sde[pos] = make_int2(eli[nPred + i], i);
}

__global__ __launch_bounds__(256)
void decode_sorted_kernel(float* __restrict__ out)
{
    __shared__ float zsrc[OUT_C];
    const int b   = blockIdx.x;
    const int tid = threadIdx.x;
    if (tid < OUT_C) zsrc[tid] = g_Z[(size_t)b * OUT_C + tid];
    __syncthreads();
    const int s0 = g_start[b];
    const int s1 = g_start[b + 1];
    const int lane = tid & 31;
    const int w    = tid >> 5;
    const float4 av = reinterpret_cast<const float4*>(zsrc)[lane];
    for (int e = s0 + w; e < s1; e += 8) {
        int2 de = g_sde[e];
        float4 bv = reinterpret_cast<const float4*>(g_Z + (size_t)de.x * OUT_C)[lane];
        float dot = av.x * bv.x + av.y * bv.y + av.z * bv.z + av.w * bv.w;
        #pragma unroll
        for (int o = 16; o; o >>= 1) dot += __shfl_xor_sync(0xffffffffu, dot, o);
        if (lane == 0) out[de.y] = dot;
    }
}

// ---------------------------------------------------------------------------
extern "C" void kernel_launch(void* const* d_in, const int* in_sizes, int n_in,
                              void* d_out, int out_size)
{
    const int*   nodeIdx = (const int*)  d_in[0];
    const float* attn    = (const float*)d_in[1];
    const int*   eli     = (const int*)  d_in[2];
    const float* emb     = (const float*)d_in[3];
    const float* W1      = (const float*)d_in[4];
    const float* b1      = (const float*)d_in[5];
    const float* W2      = (const float*)d_in[6];
    const float* b2      = (const float*)d_in[7];
    float* out = (float*)d_out;
    const int nPred = in_sizes[2] / 2;

    float *pDis, *pH, *pZ, *pPart;
    __half *pAf, *pBf;
    int* pCnt;
    cudaGetSymbolAddress((void**)&pDis,  g_dis);
    cudaGetSymbolAddress((void**)&pH,    g_H);
    cudaGetSymbolAddress((void**)&pZ,    g_Z);
    cudaGetSymbolAddress((void**)&pPart, g_part);
    cudaGetSymbolAddress((void**)&pAf,   g_Af);
    cudaGetSymbolAddress((void**)&pBf,   g_Bf);
    cudaGetSymbolAddress((void**)&pCnt,  g_cnt);

    constexpr int TC_SMEM = 3 * 2 * 32 * 136 * 2;   // 3 stages x 2 planes = 52224 B
    cudaFuncSetAttribute(tc_gemm<2>, cudaFuncAttributeMaxDynamicSharedMemorySize, TC_SMEM);
    cudaFuncSetAttribute(tc_gemm<4>, cudaFuncAttributeMaxDynamicSharedMemorySize, TC_SMEM);

    // 0) edge bucket sort
    cudaMemsetAsync(pCnt, 0, N_NODES * sizeof(int));
    hist_kernel<<<(nPred / 4 + 255) / 256, 256>>>(eli, nPred);
    scan_kernel<<<1, 1024>>>();
    scatter_kernel<<<(nPred + 255) / 256, 256>>>(eli, nPred);

    // 1) convert + deg (fused), then dis
    convert_deg_kernel<<<dim3(8, 128), 256>>>(attn);
    dis_kernel<<<N_NODES / 256, 256>>>();

    // 2) P (fp16 x 2^14) = dis ⊙ (emb[nodeIdx] @ W1)
    simt_gemm<128, 64, 16, 8, 8, true>
        <<<dim3(HID_C / 64, N_NODES / 128), 128>>>(
            emb, E_DIM_C, W1, pBf, pDis, nodeIdx, N_NODES, HID_C, E_DIM_C);

    // 3) H partials = w^T @ P'   split-K=2 (TC, 1-MMA fp16)
    tc_gemm<2><<<dim3(HID_C / 128, N_NODES / 128, 2), 256, TC_SMEM>>>(
        pAf, pBf, pPart, N_NODES, HID_C, N_NODES);
    reduce_epi_kernel<2, true>
        <<<(N_NODES * HID_C / 4 + 255) / 256, 256>>>(pPart, b1, pH, HID_C);

    // 4) Q (fp16 x 2^14) = dis ⊙ (H @ W2)
    simt_gemm<128, 64, 16, 8, 8, false>
        <<<dim3(OUT_C / 64, N_NODES / 128), 128>>>(
            pH, HID_C, W2, pBf, pDis, nullptr, N_NODES, OUT_C, HID_C);

    // 5) Z partials = w^T @ Q'   split-K=4 (TC, 1-MMA fp16)
    tc_gemm<4><<<dim3(OUT_C / 128, N_NODES / 128, 4), 256, TC_SMEM>>>(
        pAf, pBf, pPart, N_NODES, OUT_C, N_NODES);
    reduce_epi_kernel<4, false>
        <<<(N_NODES * OUT_C / 4 + 255) / 256, 256>>>(pPart, b2, pZ, OUT_C);

    // 6) decode
    decode_sorted_kernel<<<N_NODES, 256>>>(out);
}

// round 13
// speedup vs baseline: 1.5447x; 1.0049x over previous
#include <cuda_runtime.h>
#include <cuda_fp16.h>
#include <cstdint>

// ---------------------------------------------------------------------------
// Round 12: fp16 Z + sort-free warp-per-edge decode.
//   A (relu(attn)) -> fp16 plane;  B (P/Q) -> fp16 plane scaled 2^14.
//   Z stored fp16 (L2-resident, 2 MB) -> decode gathers halve; no edge sort.
//   w = relu(attn);  A_norm^T @ Y == dis ⊙ ( w^T @ (dis ⊙ Y) )
//   convert: Af = fp16(relu(attn)) + deg partials (fused)
//   P  = dis ⊙ (emb[node_idx] @ W1)        (SIMT fp32 -> fp16 ×2^14)
//   H  = relu(dis/2^14 ⊙ Σ(w^T @ P') + b1) (TC split-K=2 + reduce)
//   Q  = dis ⊙ (H @ W2)                    (SIMT fp32 -> fp16 ×2^14)
//   Zh = fp16( dis/2^14 ⊙ Σ(w^T @ Q') + b2 )  (TC split-K=4 + reduce)
//   scores[e] = dot(Zh[src], Zh[dst])      (warp per edge, coalesced out)
// ---------------------------------------------------------------------------

static constexpr int N_NODES = 8192;
static constexpr int E_DIM_C = 256;
static constexpr int HID_C   = 256;
static constexpr int OUT_C   = 128;
static constexpr float B_SCALE     = 16384.0f;       // 2^14
static constexpr float B_INV_SCALE = 1.0f / 16384.0f;

__device__ float   g_degp[128 * N_NODES];
__device__ float   g_dis [N_NODES];
__device__ __half  g_Af  [(size_t)N_NODES * N_NODES];   // 128 MB fp16 relu(attn)
__device__ __half  g_Bf  [N_NODES * HID_C];             // P/Q (scaled fp16)
__device__ float   g_H   [N_NODES * HID_C];
__device__ __half  g_Zh  [N_NODES * OUT_C];             // 2 MB fp16 Z
__device__ float   g_part[2 * N_NODES * HID_C];

// ---------------------------------------------------------------------------
// Fused convert + deg: read attn once; write relu'd fp16; col partials.
// ---------------------------------------------------------------------------
__global__ void convert_deg_kernel(const float* __restrict__ attn)
{
    int c4 = blockIdx.x * blockDim.x + threadIdx.x;
    int r0 = blockIdx.y * 64;
    float4 s = make_float4(0.f, 0.f, 0.f, 0.f);
    const float4* a = reinterpret_cast<const float4*>(attn);
    #pragma unroll 4
    for (int r = 0; r < 64; ++r) {
        size_t row = r0 + r;
        float4 v = a[row * (N_NODES / 4) + c4];
        v.x = fmaxf(v.x, 0.f); v.y = fmaxf(v.y, 0.f);
        v.z = fmaxf(v.z, 0.f); v.w = fmaxf(v.w, 0.f);
        s.x += v.x; s.y += v.y; s.z += v.z; s.w += v.w;
        __half2 h0 = __floats2half2_rn(v.x, v.y);
        __half2 h1 = __floats2half2_rn(v.z, v.w);
        uint2 packed;
        packed.x = *reinterpret_cast<uint32_t*>(&h0);
        packed.y = *reinterpret_cast<uint32_t*>(&h1);
        reinterpret_cast<uint2*>(g_Af)[(row * N_NODES) / 4 + c4] = packed;
    }
    reinterpret_cast<float4*>(g_degp)[blockIdx.y * (N_NODES / 4) + c4] = s;
}

__global__ void dis_kernel()
{
    int col = blockIdx.x * blockDim.x + threadIdx.x;
    float s = 0.f;
    #pragma unroll
    for (int r = 0; r < 128; ++r) s += g_degp[(size_t)r * N_NODES + col];
    g_dis[col] = (s > 0.f) ? rsqrtf(s) : 0.f;
}

// ---------------------------------------------------------------------------
__device__ __forceinline__ void ldsm_x4_t(uint32_t& r0, uint32_t& r1,
                                          uint32_t& r2, uint32_t& r3, uint32_t addr)
{
    asm volatile("ldmatrix.sync.aligned.m8n8.x4.trans.shared.b16 {%0,%1,%2,%3}, [%4];"
                 : "=r"(r0), "=r"(r1), "=r"(r2), "=r"(r3) : "r"(addr));
}

__device__ __forceinline__ void mma16816h(float* d, const uint32_t* a, const uint32_t* b)
{
    asm volatile("mma.sync.aligned.m16n8k16.row.col.f32.f16.f16.f32 "
                 "{%0,%1,%2,%3}, {%4,%5,%6,%7}, {%8,%9}, {%0,%1,%2,%3};"
                 : "+f"(d[0]), "+f"(d[1]), "+f"(d[2]), "+f"(d[3])
                 : "r"(a[0]), "r"(a[1]), "r"(a[2]), "r"(a[3]), "r"(b[0]), "r"(b[1]));
}

__device__ __forceinline__ void cpasync16(uint32_t smem, const void* gmem)
{
    asm volatile("cp.async.cg.shared.global [%0], [%1], 16;" :: "r"(smem), "l"(gmem));
}

// ---------------------------------------------------------------------------
// TC GEMM:  Cpart[z] = Af^T(ish) @ Bf   (1 MMA per k16 step per subtile)
// BM=128, BN=128, BK=32, 256 threads, warp tile 64x32; 3-stage cp.async,
// 2 planes per stage, 2 CTAs/SM.
// ---------------------------------------------------------------------------
template<int SPLITK>
__global__ __launch_bounds__(256, 2)
void tc_gemm(const __half* __restrict__ Afg,
             const __half* __restrict__ Bfg,
             float* __restrict__ Cpart, int M, int N, int K)
{
    constexpr int BM = 128, BN = 128, BK = 32;
    constexpr int AP = 136;
    constexpr int STG = BK * AP;
    constexpr int NSTAGE = 3;

    extern __shared__ __half smheap[];
    auto plane = [&](int s, int p) { return smheap + (s * 2 + p) * STG; };

    const int tid  = threadIdx.x;
    const int lane = tid & 31;
    const int wid  = tid >> 5;
    const int wm   = (wid >> 2) * 64;
    const int wn   = (wid & 3) * 32;
    const int m0   = blockIdx.y * BM;
    const int n0   = blockIdx.x * BN;
    const int Ksp  = K / SPLITK;
    const int kB   = blockIdx.z * Ksp;
    const int KT   = Ksp / BK;

    float acc[4][4][4];
    #pragma unroll
    for (int i = 0; i < 4; ++i)
        #pragma unroll
        for (int j = 0; j < 4; ++j)
            #pragma unroll
            for (int q = 0; q < 4; ++q) acc[i][j][q] = 0.f;

    auto issue = [&](int kt, int s) {
        int kg = kB + kt * BK;
        uint32_t base = (uint32_t)__cvta_generic_to_shared(plane(s, 0));
        #pragma unroll
        for (int v = 0; v < 2; ++v) {
            int idx  = tid + v * 256;
            int row  = idx >> 4;
            int c16  = idx & 15;
            uint32_t so = row * (AP * 2) + c16 * 16;
            size_t   aoff = (size_t)(kg + row) * M + m0 + c16 * 8;
            size_t   boff = (size_t)(kg + row) * N + n0 + c16 * 8;
            cpasync16(base + 0 * STG * 2 + so, Afg + aoff);
            cpasync16(base + 1 * STG * 2 + so, Bfg + boff);
        }
        asm volatile("cp.async.commit_group;");
    };

    const int aRow = (lane & 7) + ((lane >> 4) & 1) * 8;
    const int aCol = wm + ((lane >> 3) & 1) * 8;
    const int bRow = (lane & 7) + ((lane >> 3) & 1) * 8;
    const int bCol = wn + ((lane >> 4) & 1) * 8;

    auto compute = [&](int s) {
        uint32_t afB = (uint32_t)__cvta_generic_to_shared(plane(s, 0));
        uint32_t bfB = (uint32_t)__cvta_generic_to_shared(plane(s, 1));
        #pragma unroll
        for (int k16 = 0; k16 < 2; ++k16) {
            int k0 = k16 * 16;
            uint32_t bf[4][2];
            #pragma unroll
            for (int p = 0; p < 2; ++p) {
                uint32_t off = ((k0 + bRow) * AP + bCol + p * 16) * 2;
                uint32_t r0, r1, r2, r3;
                ldsm_x4_t(r0, r1, r2, r3, bfB + off);
                bf[2 * p][0] = r0; bf[2 * p][1] = r1;
                bf[2 * p + 1][0] = r2; bf[2 * p + 1][1] = r3;
            }
            #pragma unroll
            for (int mi = 0; mi < 4; ++mi) {
                uint32_t af[4];
                uint32_t off = ((k0 + aRow) * AP + aCol + mi * 16) * 2;
                ldsm_x4_t(af[0], af[1], af[2], af[3], afB + off);
                #pragma unroll
                for (int ni = 0; ni < 4; ++ni)
                    mma16816h(acc[mi][ni], af, bf[ni]);
            }
        }
    };

    issue(0, 0);
    if (KT > 1) issue(1, 1);
    if (KT > 2) issue(2, 2);

    for (int kt = 0; kt < KT; ++kt) {
        asm volatile("cp.async.wait_group %0;" :: "n"(NSTAGE - 2));
        __syncthreads();
        compute(kt % NSTAGE);
        __syncthreads();
        if (kt + NSTAGE < KT) {
            issue(kt + NSTAGE, kt % NSTAGE);
        } else if (kt + 1 < KT) {
            asm volatile("cp.async.commit_group;");
        }
    }

    float* Cp = Cpart + (size_t)blockIdx.z * M * N;
    const int rB = m0 + wm + (lane >> 2);
    const int cB = n0 + wn + (lane & 3) * 2;
    #pragma unroll
    for (int mi = 0; mi < 4; ++mi)
        #pragma unroll
        for (int ni = 0; ni < 4; ++ni) {
            int r = rB + mi * 16;
            int c = cB + ni * 8;
            *reinterpret_cast<float2*>(Cp + (size_t)r * N + c) =
                make_float2(acc[mi][ni][0], acc[mi][ni][1]);
            *reinterpret_cast<float2*>(Cp + (size_t)(r + 8) * N + c) =
                make_float2(acc[mi][ni][2], acc[mi][ni][3]);
        }
}

// ---------------------------------------------------------------------------
// Split-K reduce + epilogue for H (fp32 out, relu).
// ---------------------------------------------------------------------------
__global__ void reduce_epi_h_kernel(const float* __restrict__ part,
                                    const float* __restrict__ bias)
{
    int i4 = blockIdx.x * blockDim.x + threadIdx.x;
    constexpr int N = HID_C;
    constexpr int MN4 = N_NODES * N / 4;
    if (i4 >= MN4) return;
    const float4* p = reinterpret_cast<const float4*>(part);
    float4 s = p[i4];
    float4 v = p[i4 + (size_t)MN4];
    s.x += v.x; s.y += v.y; s.z += v.z; s.w += v.w;
    int row = (i4 * 4) / N;
    int col = (i4 * 4) % N;
    float sc = g_dis[row] * B_INV_SCALE;
    float4 bb = *reinterpret_cast<const float4*>(bias + col);
    float4 r;
    r.x = fmaxf(s.x * sc + bb.x, 0.f);
    r.y = fmaxf(s.y * sc + bb.y, 0.f);
    r.z = fmaxf(s.z * sc + bb.z, 0.f);
    r.w = fmaxf(s.w * sc + bb.w, 0.f);
    reinterpret_cast<float4*>(g_H)[i4] = r;
}

// ---------------------------------------------------------------------------
// Split-K reduce + epilogue for Z -> fp16 output.
// ---------------------------------------------------------------------------
__global__ void reduce_epi_z_kernel(const float* __restrict__ part,
                                    const float* __restrict__ bias)
{
    int i4 = blockIdx.x * blockDim.x + threadIdx.x;
    constexpr int N = OUT_C;
    constexpr int MN4 = N_NODES * N / 4;
    if (i4 >= MN4) return;
    const float4* p = reinterpret_cast<const float4*>(part);
    float4 s = p[i4];
    #pragma unroll
    for (int sp = 1; sp < 4; ++sp) {
        float4 v = p[i4 + (size_t)sp * MN4];
        s.x += v.x; s.y += v.y; s.z += v.z; s.w += v.w;
    }
    int row = (i4 * 4) / N;
    int col = (i4 * 4) % N;
    float sc = g_dis[row] * B_INV_SCALE;
    float4 bb = *reinterpret_cast<const float4*>(bias + col);
    __half2 h0 = __floats2half2_rn(s.x * sc + bb.x, s.y * sc + bb.y);
    __half2 h1 = __floats2half2_rn(s.z * sc + bb.z, s.w * sc + bb.w);
    uint2 packed;
    packed.x = *reinterpret_cast<uint32_t*>(&h0);
    packed.y = *reinterpret_cast<uint32_t*>(&h1);
    reinterpret_cast<uint2*>(g_Zh)[i4] = packed;
}

// ---------------------------------------------------------------------------
// SIMT fp32 GEMM; epilogue writes one scaled fp16 plane.
// ---------------------------------------------------------------------------
template<int BM, int BN, int BK, int TM, int TN, bool GATHER_A>
__global__ __launch_bounds__((BM / TM) * (BN / TN))
void simt_gemm(const float* __restrict__ A, int lda,
               const float* __restrict__ B,
               __half* __restrict__ Cf,
               const float* __restrict__ rowScale,
               const int* __restrict__ gatherIdx,
               int M, int N, int K)
{
    constexpr int NT   = (BM / TM) * (BN / TN);
    constexpr int APAD = 4;
    constexpr int AV   = (BM * BK) / (4 * NT);
    constexpr int BV   = (BK * BN) / (4 * NT);

    __shared__ float As[BK][BM + APAD];
    __shared__ float Bs[BK][BN];

    const int tid = threadIdx.x;
    const int tx  = tid % (BN / TN);
    const int ty  = tid / (BN / TN);
    const int m0  = blockIdx.y * BM;
    const int n0  = blockIdx.x * BN;

    float4 areg[AV], breg[BV];
    float acc[TM][TN];
    #pragma unroll
    for (int i = 0; i < TM; ++i)
        #pragma unroll
        for (int j = 0; j < TN; ++j) acc[i][j] = 0.f;

    auto loadA = [&](int k0) {
        #pragma unroll
        for (int v = 0; v < AV; ++v) {
            int idx = tid + v * NT;
            int m  = idx / (BK / 4);
            int kq = idx % (BK / 4);
            int row = GATHER_A ? gatherIdx[m0 + m] : (m0 + m);
            areg[v] = *reinterpret_cast<const float4*>(A + (size_t)row * lda + (k0 + kq * 4));
        }
    };
    auto storeA = [&]() {
        #pragma unroll
        for (int v = 0; v < AV; ++v) {
            int idx = tid + v * NT;
            int m  = idx / (BK / 4);
            int kq = idx % (BK / 4);
            As[kq * 4 + 0][m] = areg[v].x;
            As[kq * 4 + 1][m] = areg[v].y;
            As[kq * 4 + 2][m] = areg[v].z;
            As[kq * 4 + 3][m] = areg[v].w;
        }
    };
    auto loadB = [&](int k0) {
        #pragma unroll
        for (int v = 0; v < BV; ++v) {
            int idx = tid + v * NT;
            int k  = idx / (BN / 4);
            int n4 = idx % (BN / 4);
            breg[v] = *reinterpret_cast<const float4*>(B + (size_t)(k0 + k) * N + (n0 + n4 * 4));
        }
    };
    auto storeB = [&]() {
        #pragma unroll
        for (int v = 0; v < BV; ++v) {
            int idx = tid + v * NT;
            int k  = idx / (BN / 4);
            int n4 = idx % (BN / 4);
            *reinterpret_cast<float4*>(&Bs[k][n4 * 4]) = breg[v];
        }
    };

    loadA(0); loadB(0);
    storeA(); storeB();
    __syncthreads();

    const int KT = K / BK;
    for (int kt = 0; kt < KT; ++kt) {
        if (kt + 1 < KT) { loadA((kt + 1) * BK); loadB((kt + 1) * BK); }
        #pragma unroll
        for (int kk = 0; kk < BK; ++kk) {
            float a[TM], b[TN];
            #pragma unroll
            for (int i = 0; i < TM; i += 4) {
                float4 t = *reinterpret_cast<const float4*>(&As[kk][ty * TM + i]);
                a[i] = t.x; a[i + 1] = t.y; a[i + 2] = t.z; a[i + 3] = t.w;
            }
            #pragma unroll
            for (int j = 0; j < TN; j += 4) {
                float4 t = *reinterpret_cast<const float4*>(&Bs[kk][tx * TN + j]);
                b[j] = t.x; b[j + 1] = t.y; b[j + 2] = t.z; b[j + 3] = t.w;
            }
            #pragma unroll
            for (int i = 0; i < TM; ++i)
                #pragma unroll
                for (int j = 0; j < TN; ++j)
                    acc[i][j] = fmaf(a[i], b[j], acc[i][j]);
        }
        if (kt + 1 < KT) {
            __syncthreads();
            storeA(); storeB();
            __syncthreads();
        }
    }

    #pragma unroll
    for (int i = 0; i < TM; ++i) {
        int row = m0 + ty * TM + i;
        float sc = rowScale[row] * B_SCALE;
        #pragma unroll
        for (int j = 0; j < TN; j += 4) {
            int col = n0 + tx * TN + j;
            __half h[4];
            h[0] = __float2half_rn(acc[i][j + 0] * sc);
            h[1] = __float2half_rn(acc[i][j + 1] * sc);
            h[2] = __float2half_rn(acc[i][j + 2] * sc);
            h[3] = __float2half_rn(acc[i][j + 3] * sc);
            reinterpret_cast<uint2*>(Cf)[((size_t)row * N + col) / 4] =
                *reinterpret_cast<uint2*>(h);
        }
    }
}

// ---------------------------------------------------------------------------
// decode: warp per edge, fp16 Z rows (L2-resident), coalesced out writes.
// Each lane loads 4 halves (8 B) from each endpoint row.
// ---------------------------------------------------------------------------
__global__ __launch_bounds__(256)
void decode_kernel(const int* __restrict__ eli,
                   float* __restrict__ out, int nPred)
{
    int warp = (blockIdx.x * blockDim.x + threadIdx.x) >> 5;
    int lane = threadIdx.x & 31;
    if (warp >= nPred) return;
    int s = __ldg(eli + warp);
    int d = __ldg(eli + nPred + warp);
    const uint2* zs = reinterpret_cast<const uint2*>(g_Zh + (size_t)s * OUT_C);
    const uint2* zd = reinterpret_cast<const uint2*>(g_Zh + (size_t)d * OUT_C);
    uint2 ar = __ldg(zs + lane);
    uint2 br = __ldg(zd + lane);
    __half2 a0 = *reinterpret_cast<__half2*>(&ar.x);
    __half2 a1 = *reinterpret_cast<__half2*>(&ar.y);
    __half2 b0 = *reinterpret_cast<__half2*>(&br.x);
    __half2 b1 = *reinterpret_cast<__half2*>(&br.y);
    float2 af0 = __half22float2(a0), af1 = __half22float2(a1);
    float2 bf0 = __half22float2(b0), bf1 = __half22float2(b1);
    float dot = af0.x * bf0.x + af0.y * bf0.y + af1.x * bf1.x + af1.y * bf1.y;
    #pragma unroll
    for (int o = 16; o; o >>= 1) dot += __shfl_xor_sync(0xffffffffu, dot, o);
    if (lane == 0) out[warp] = dot;
}

// ---------------------------------------------------------------------------
extern "C" void kernel_launch(void* const* d_in, const int* in_sizes, int n_in,
                              void* d_out, int out_size)
{
    const int*   nodeIdx = (const int*)  d_in[0];
    const float* attn    = (const float*)d_in[1];
    const int*   eli     = (const int*)  d_in[2];
    const float* emb     = (const float*)d_in[3];
    const float* W1      = (const float*)d_in[4];
    const float* b1      = (const float*)d_in[5];
    const float* W2      = (const float*)d_in[6];
    const float* b2      = (const float*)d_in[7];
    float* out = (float*)d_out;
    const int nPred = in_sizes[2] / 2;

    float *pDis, *pH, *pPart;
    __half *pAf, *pBf;
    cudaGetSymbolAddress((void**)&pDis,  g_dis);
    cudaGetSymbolAddress((void**)&pH,    g_H);
    cudaGetSymbolAddress((void**)&pPart, g_part);
    cudaGetSymbolAddress((void**)&pAf,   g_Af);
    cudaGetSymbolAddress((void**)&pBf,   g_Bf);

    constexpr int TC_SMEM = 3 * 2 * 32 * 136 * 2;   // 52224 B
    cudaFuncSetAttribute(tc_gemm<2>, cudaFuncAttributeMaxDynamicSharedMemorySize, TC_SMEM);
    cudaFuncSetAttribute(tc_gemm<4>, cudaFuncAttributeMaxDynamicSharedMemorySize, TC_SMEM);

    // 1) convert + deg (fused), then dis
    convert_deg_kernel<<<dim3(8, 128), 256>>>(attn);
    dis_kernel<<<N_NODES / 256, 256>>>();

    // 2) P (fp16 x 2^14) = dis ⊙ (emb[nodeIdx] @ W1)
    simt_gemm<128, 64, 16, 8, 8, true>
        <<<dim3(HID_C / 64, N_NODES / 128), 128>>>(
            emb, E_DIM_C, W1, pBf, pDis, nodeIdx, N_NODES, HID_C, E_DIM_C);

    // 3) H partials = w^T @ P'   split-K=2 (TC)
    tc_gemm<2><<<dim3(HID_C / 128, N_NODES / 128, 2), 256, TC_SMEM>>>(
        pAf, pBf, pPart, N_NODES, HID_C, N_NODES);
    reduce_epi_h_kernel<<<(N_NODES * HID_C / 4 + 255) / 256, 256>>>(pPart, b1);

    // 4) Q (fp16 x 2^14) = dis ⊙ (H @ W2)
    simt_gemm<128, 64, 16, 8, 8, false>
        <<<dim3(OUT_C / 64, N_NODES / 128), 128>>>(
            pH, HID_C, W2, pBf, pDis, nullptr, N_NODES, OUT_C, HID_C);

    // 5) Z partials = w^T @ Q'   split-K=4 (TC) -> fp16 Z
    tc_gemm<4><<<dim3(OUT_C / 128, N_NODES / 128, 4), 256, TC_SMEM>>>(
        pAf, pBf, pPart, N_NODES, OUT_C, N_NODES);
    reduce_epi_z_kernel<<<(N_NODES * OUT_C / 4 + 255) / 256, 256>>>(pPart, b2);

    // 6) decode (warp per edge, fp16 gathers, coalesced out)
    decode_kernel<<<(nPred + 7) / 8, 256>>>(eli, out, nPred);
}

// round 14
// speedup vs baseline: 1.8188x; 1.1775x over previous
#include <cuda_runtime.h>
#include <cuda_fp16.h>
#include <cstdint>

// ---------------------------------------------------------------------------
// Round 13: 64x64 warp tiles in both TC GEMMs; 16-lane decode.
//   A (relu(attn)) -> fp16 plane;  B (P/Q) -> fp16 plane scaled 2^14.
//   Z stored fp16 (L2-resident); warp-pair decode.
//   w = relu(attn);  A_norm^T @ Y == dis ⊙ ( w^T @ (dis ⊙ Y) )
// ---------------------------------------------------------------------------

static constexpr int N_NODES = 8192;
static constexpr int E_DIM_C = 256;
static constexpr int HID_C   = 256;
static constexpr int OUT_C   = 128;
static constexpr float B_SCALE     = 16384.0f;       // 2^14
static constexpr float B_INV_SCALE = 1.0f / 16384.0f;

__device__ float   g_degp[128 * N_NODES];
__device__ float   g_dis [N_NODES];
__device__ __half  g_Af  [(size_t)N_NODES * N_NODES];   // 128 MB fp16 relu(attn)
__device__ __half  g_Bf  [N_NODES * HID_C];             // P/Q (scaled fp16)
__device__ float   g_H   [N_NODES * HID_C];
__device__ __half  g_Zh  [N_NODES * OUT_C];             // 2 MB fp16 Z
__device__ float   g_part[4 * N_NODES * OUT_C];         // split-K partials

// ---------------------------------------------------------------------------
__global__ void convert_deg_kernel(const float* __restrict__ attn)
{
    int c4 = blockIdx.x * blockDim.x + threadIdx.x;
    int r0 = blockIdx.y * 64;
    float4 s = make_float4(0.f, 0.f, 0.f, 0.f);
    const float4* a = reinterpret_cast<const float4*>(attn);
    #pragma unroll 4
    for (int r = 0; r < 64; ++r) {
        size_t row = r0 + r;
        float4 v = a[row * (N_NODES / 4) + c4];
        v.x = fmaxf(v.x, 0.f); v.y = fmaxf(v.y, 0.f);
        v.z = fmaxf(v.z, 0.f); v.w = fmaxf(v.w, 0.f);
        s.x += v.x; s.y += v.y; s.z += v.z; s.w += v.w;
        __half2 h0 = __floats2half2_rn(v.x, v.y);
        __half2 h1 = __floats2half2_rn(v.z, v.w);
        uint2 packed;
        packed.x = *reinterpret_cast<uint32_t*>(&h0);
        packed.y = *reinterpret_cast<uint32_t*>(&h1);
        reinterpret_cast<uint2*>(g_Af)[(row * N_NODES) / 4 + c4] = packed;
    }
    reinterpret_cast<float4*>(g_degp)[blockIdx.y * (N_NODES / 4) + c4] = s;
}

__global__ void dis_kernel()
{
    int col = blockIdx.x * blockDim.x + threadIdx.x;
    float s = 0.f;
    #pragma unroll
    for (int r = 0; r < 128; ++r) s += g_degp[(size_t)r * N_NODES + col];
    g_dis[col] = (s > 0.f) ? rsqrtf(s) : 0.f;
}

// ---------------------------------------------------------------------------
__device__ __forceinline__ void ldsm_x4_t(uint32_t& r0, uint32_t& r1,
                                          uint32_t& r2, uint32_t& r3, uint32_t addr)
{
    asm volatile("ldmatrix.sync.aligned.m8n8.x4.trans.shared.b16 {%0,%1,%2,%3}, [%4];"
                 : "=r"(r0), "=r"(r1), "=r"(r2), "=r"(r3) : "r"(addr));
}

__device__ __forceinline__ void mma16816h(float* d, const uint32_t* a, const uint32_t* b)
{
    asm volatile("mma.sync.aligned.m16n8k16.row.col.f32.f16.f16.f32 "
                 "{%0,%1,%2,%3}, {%4,%5,%6,%7}, {%8,%9}, {%0,%1,%2,%3};"
                 : "+f"(d[0]), "+f"(d[1]), "+f"(d[2]), "+f"(d[3])
                 : "r"(a[0]), "r"(a[1]), "r"(a[2]), "r"(a[3]), "r"(b[0]), "r"(b[1]));
}

__device__ __forceinline__ void cpasync16(uint32_t smem, const void* gmem)
{
    asm volatile("cp.async.cg.shared.global [%0], [%1], 16;" :: "r"(smem), "l"(gmem));
}

// ---------------------------------------------------------------------------
// TC GEMM, 64x64 warp tile.
//   NT threads (NT/32 warps in 2 x (NT/64) grid), BM=128, BN template, BK=32.
//   Af: [K, M] fp16, Bf: [K, Ntot] fp16 (pre-scaled). 3-stage cp.async.
// ---------------------------------------------------------------------------
template<int SPLITK, int NT, int BN, int MAXCTA>
__global__ __launch_bounds__(NT, MAXCTA)
void tc_gemm(const __half* __restrict__ Afg,
             const __half* __restrict__ Bfg,
             float* __restrict__ Cpart, int M, int Ntot, int K)
{
    constexpr int BM = 128, BK = 32;
    constexpr int AP = 136;
    constexpr int BP = BN + 8;
    constexpr int ASTG = BK * AP;                 // halves
    constexpr int BSTG = BK * BP;
    constexpr int NSTAGE = 3;
    constexpr int WCOLS = NT / 64;                // warps per row of warp-grid
    constexpr int CA = 512 / NT;                  // A 16B-chunks per thread
    constexpr int CB = (4 * BN) / NT;             // B 16B-chunks per thread
    constexpr int BC8 = BN / 8;                   // B chunks per row

    extern __shared__ __half smheap[];
    auto planeA = [&](int s) { return smheap + s * (ASTG + BSTG); };
    auto planeB = [&](int s) { return smheap + s * (ASTG + BSTG) + ASTG; };

    const int tid  = threadIdx.x;
    const int lane = tid & 31;
    const int wid  = tid >> 5;
    const int wm   = (wid / WCOLS) * 64;
    const int wn   = (wid % WCOLS) * 64;
    const int m0   = blockIdx.y * BM;
    const int n0   = blockIdx.x * BN;
    const int Ksp  = K / SPLITK;
    const int kB   = blockIdx.z * Ksp;
    const int KT   = Ksp / BK;

    float acc[4][8][4];
    #pragma unroll
    for (int i = 0; i < 4; ++i)
        #pragma unroll
        for (int j = 0; j < 8; ++j)
            #pragma unroll
            for (int q = 0; q < 4; ++q) acc[i][j][q] = 0.f;

    auto issue = [&](int kt, int s) {
        int kg = kB + kt * BK;
        uint32_t ab = (uint32_t)__cvta_generic_to_shared(planeA(s));
        uint32_t bb = (uint32_t)__cvta_generic_to_shared(planeB(s));
        #pragma unroll
        for (int v = 0; v < CA; ++v) {
            int idx = tid + v * NT;
            int row = idx >> 4;
            int c16 = idx & 15;
            cpasync16(ab + row * (AP * 2) + c16 * 16,
                      Afg + (size_t)(kg + row) * M + m0 + c16 * 8);
        }
        #pragma unroll
        for (int v = 0; v < CB; ++v) {
            int idx = tid + v * NT;
            int row = idx / BC8;
            int cc  = idx % BC8;
            cpasync16(bb + row * (BP * 2) + cc * 16,
                      Bfg + (size_t)(kg + row) * Ntot + n0 + cc * 8);
        }
        asm volatile("cp.async.commit_group;");
    };

    const int aRow = (lane & 7) + ((lane >> 4) & 1) * 8;
    const int aCol = wm + ((lane >> 3) & 1) * 8;
    const int bRow = (lane & 7) + ((lane >> 3) & 1) * 8;
    const int bCol = wn + ((lane >> 4) & 1) * 8;

    auto compute = [&](int s) {
        uint32_t ab = (uint32_t)__cvta_generic_to_shared(planeA(s));
        uint32_t bb = (uint32_t)__cvta_generic_to_shared(planeB(s));
        #pragma unroll
        for (int k16 = 0; k16 < 2; ++k16) {
            int k0 = k16 * 16;
            uint32_t bf[8][2];
            #pragma unroll
            for (int p = 0; p < 4; ++p) {
                uint32_t off = ((k0 + bRow) * BP + bCol + p * 16) * 2;
                uint32_t r0, r1, r2, r3;
                ldsm_x4_t(r0, r1, r2, r3, bb + off);
                bf[2 * p][0] = r0; bf[2 * p][1] = r1;
                bf[2 * p + 1][0] = r2; bf[2 * p + 1][1] = r3;
            }
            #pragma unroll
            for (int mi = 0; mi < 4; ++mi) {
                uint32_t af[4];
                uint32_t off = ((k0 + aRow) * AP + aCol + mi * 16) * 2;
                ldsm_x4_t(af[0], af[1], af[2], af[3], ab + off);
                #pragma unroll
                for (int ni = 0; ni < 8; ++ni)
                    mma16816h(acc[mi][ni], af, bf[ni]);
            }
        }
    };

    issue(0, 0);
    if (KT > 1) issue(1, 1);
    if (KT > 2) issue(2, 2);

    for (int kt = 0; kt < KT; ++kt) {
        asm volatile("cp.async.wait_group %0;" :: "n"(NSTAGE - 2));
        __syncthreads();
        compute(kt % NSTAGE);
        __syncthreads();
        if (kt + NSTAGE < KT) {
            issue(kt + NSTAGE, kt % NSTAGE);
        } else if (kt + 1 < KT) {
            asm volatile("cp.async.commit_group;");
        }
    }

    float* Cp = Cpart + (size_t)blockIdx.z * M * Ntot;
    const int rB = m0 + wm + (lane >> 2);
    const int cB = n0 + wn + (lane & 3) * 2;
    #pragma unroll
    for (int mi = 0; mi < 4; ++mi)
        #pragma unroll
        for (int ni = 0; ni < 8; ++ni) {
            int r = rB + mi * 16;
            int c = cB + ni * 8;
            *reinterpret_cast<float2*>(Cp + (size_t)r * Ntot + c) =
                make_float2(acc[mi][ni][0], acc[mi][ni][1]);
            *reinterpret_cast<float2*>(Cp + (size_t)(r + 8) * Ntot + c) =
                make_float2(acc[mi][ni][2], acc[mi][ni][3]);
        }
}

// ---------------------------------------------------------------------------
__global__ void reduce_epi_h_kernel(const float* __restrict__ part,
                                    const float* __restrict__ bias)
{
    int i4 = blockIdx.x * blockDim.x + threadIdx.x;
    constexpr int N = HID_C;
    constexpr int MN4 = N_NODES * N / 4;
    if (i4 >= MN4) return;
    const float4* p = reinterpret_cast<const float4*>(part);
    float4 s = p[i4];
    float4 v = p[i4 + (size_t)MN4];
    s.x += v.x; s.y += v.y; s.z += v.z; s.w += v.w;
    int row = (i4 * 4) / N;
    int col = (i4 * 4) % N;
    float sc = g_dis[row] * B_INV_SCALE;
    float4 bb = *reinterpret_cast<const float4*>(bias + col);
    float4 r;
    r.x = fmaxf(s.x * sc + bb.x, 0.f);
    r.y = fmaxf(s.y * sc + bb.y, 0.f);
    r.z = fmaxf(s.z * sc + bb.z, 0.f);
    r.w = fmaxf(s.w * sc + bb.w, 0.f);
    reinterpret_cast<float4*>(g_H)[i4] = r;
}

__global__ void reduce_epi_z_kernel(const float* __restrict__ part,
                                    const float* __restrict__ bias)
{
    int i4 = blockIdx.x * blockDim.x + threadIdx.x;
    constexpr int N = OUT_C;
    constexpr int MN4 = N_NODES * N / 4;
    if (i4 >= MN4) return;
    const float4* p = reinterpret_cast<const float4*>(part);
    float4 s = p[i4];
    #pragma unroll
    for (int sp = 1; sp < 4; ++sp) {
        float4 v = p[i4 + (size_t)sp * MN4];
        s.x += v.x; s.y += v.y; s.z += v.z; s.w += v.w;
    }
    int row = (i4 * 4) / N;
    int col = (i4 * 4) % N;
    float sc = g_dis[row] * B_INV_SCALE;
    float4 bb = *reinterpret_cast<const float4*>(bias + col);
    __half2 h0 = __floats2half2_rn(s.x * sc + bb.x, s.y * sc + bb.y);
    __half2 h1 = __floats2half2_rn(s.z * sc + bb.z, s.w * sc + bb.w);
    uint2 packed;
    packed.x = *reinterpret_cast<uint32_t*>(&h0);
    packed.y = *reinterpret_cast<uint32_t*>(&h1);
    reinterpret_cast<uint2*>(g_Zh)[i4] = packed;
}

// ---------------------------------------------------------------------------
template<int BM, int BN, int BK, int TM, int TN, bool GATHER_A>
__global__ __launch_bounds__((BM / TM) * (BN / TN))
void simt_gemm(const float* __restrict__ A, int lda,
               const float* __restrict__ B,
               __half* __restrict__ Cf,
               const float* __restrict__ rowScale,
               const int* __restrict__ gatherIdx,
               int M, int N, int K)
{
    constexpr int NT   = (BM / TM) * (BN / TN);
    constexpr int APAD = 4;
    constexpr int AV   = (BM * BK) / (4 * NT);
    constexpr int BV   = (BK * BN) / (4 * NT);

    __shared__ float As[BK][BM + APAD];
    __shared__ float Bs[BK][BN];

    const int tid = threadIdx.x;
    const int tx  = tid % (BN / TN);
    const int ty  = tid / (BN / TN);
    const int m0  = blockIdx.y * BM;
    const int n0  = blockIdx.x * BN;

    float4 areg[AV], breg[BV];
    float acc[TM][TN];
    #pragma unroll
    for (int i = 0; i < TM; ++i)
        #pragma unroll
        for (int j = 0; j < TN; ++j) acc[i][j] = 0.f;

    auto loadA = [&](int k0) {
        #pragma unroll
        for (int v = 0; v < AV; ++v) {
            int idx = tid + v * NT;
            int m  = idx / (BK / 4);
            int kq = idx % (BK / 4);
            int row = GATHER_A ? gatherIdx[m0 + m] : (m0 + m);
            areg[v] = *reinterpret_cast<const float4*>(A + (size_t)row * lda + (k0 + kq * 4));
        }
    };
    auto storeA = [&]() {
        #pragma unroll
        for (int v = 0; v < AV; ++v) {
            int idx = tid + v * NT;
            int m  = idx / (BK / 4);
            int kq = idx % (BK / 4);
            As[kq * 4 + 0][m] = areg[v].x;
            As[kq * 4 + 1][m] = areg[v].y;
            As[kq * 4 + 2][m] = areg[v].z;
            As[kq * 4 + 3][m] = areg[v].w;
        }
    };
    auto loadB = [&](int k0) {
        #pragma unroll
        for (int v = 0; v < BV; ++v) {
            int idx = tid + v * NT;
            int k  = idx / (BN / 4);
            int n4 = idx % (BN / 4);
            breg[v] = *reinterpret_cast<const float4*>(B + (size_t)(k0 + k) * N + (n0 + n4 * 4));
        }
    };
    auto storeB = [&]() {
        #pragma unroll
        for (int v = 0; v < BV; ++v) {
            int idx = tid + v * NT;
            int k  = idx / (BN / 4);
            int n4 = idx % (BN / 4);
            *reinterpret_cast<float4*>(&Bs[k][n4 * 4]) = breg[v];
        }
    };

    loadA(0); loadB(0);
    storeA(); storeB();
    __syncthreads();

    const int KT = K / BK;
    for (int kt = 0; kt < KT; ++kt) {
        if (kt + 1 < KT) { loadA((kt + 1) * BK); loadB((kt + 1) * BK); }
        #pragma unroll
        for (int kk = 0; kk < BK; ++kk) {
            float a[TM], b[TN];
            #pragma unroll
            for (int i = 0; i < TM; i += 4) {
                float4 t = *reinterpret_cast<const float4*>(&As[kk][ty * TM + i]);
                a[i] = t.x; a[i + 1] = t.y; a[i + 2] = t.z; a[i + 3] = t.w;
            }
            #pragma unroll
            for (int j = 0; j < TN; j += 4) {
                float4 t = *reinterpret_cast<const float4*>(&Bs[kk][tx * TN + j]);
                b[j] = t.x; b[j + 1] = t.y; b[j + 2] = t.z; b[j + 3] = t.w;
            }
            #pragma unroll
            for (int i = 0; i < TM; ++i)
                #pragma unroll
                for (int j = 0; j < TN; ++j)
                    acc[i][j] = fmaf(a[i], b[j], acc[i][j]);
        }
        if (kt + 1 < KT) {
            __syncthreads();
            storeA(); storeB();
            __syncthreads();
        }
    }

    #pragma unroll
    for (int i = 0; i < TM; ++i) {
        int row = m0 + ty * TM + i;
        float sc = rowScale[row] * B_SCALE;
        #pragma unroll
        for (int j = 0; j < TN; j += 4) {
            int col = n0 + tx * TN + j;
            __half h[4];
            h[0] = __float2half_rn(acc[i][j + 0] * sc);
            h[1] = __float2half_rn(acc[i][j + 1] * sc);
            h[2] = __float2half_rn(acc[i][j + 2] * sc);
            h[3] = __float2half_rn(acc[i][j + 3] * sc);
            reinterpret_cast<uint2*>(Cf)[((size_t)row * N + col) / 4] =
                *reinterpret_cast<uint2*>(h);
        }
    }
}

// ---------------------------------------------------------------------------
// decode: 16 lanes per edge (2 edges per warp), uint4 (16B) loads of fp16 Z.
// ---------------------------------------------------------------------------
__global__ __launch_bounds__(256)
void decode_kernel(const int* __restrict__ eli,
                   float* __restrict__ out, int nPred)
{
    int g = blockIdx.x * blockDim.x + threadIdx.x;
    int e = g >> 4;                    // edge index (16 lanes per edge)
    int l16 = threadIdx.x & 15;
    if (e >= nPred) return;
    int s = __ldg(eli + e);
    int d = __ldg(eli + nPred + e);
    const uint4* zs = reinterpret_cast<const uint4*>(g_Zh + (size_t)s * OUT_C);
    const uint4* zd = reinterpret_cast<const uint4*>(g_Zh + (size_t)d * OUT_C);
    uint4 ar = __ldg(zs + l16);
    uint4 br = __ldg(zd + l16);
    float dot = 0.f;
    const uint32_t* au = &ar.x;
    const uint32_t* bu = &br.x;
    #pragma unroll
    for (int q = 0; q < 4; ++q) {
        __half2 ah = *reinterpret_cast<const __half2*>(&au[q]);
        __half2 bh = *reinterpret_cast<const __half2*>(&bu[q]);
        float2 af = __half22float2(ah);
        float2 bf = __half22float2(bh);
        dot += af.x * bf.x + af.y * bf.y;
    }
    #pragma unroll
    for (int o = 8; o; o >>= 1) dot += __shfl_xor_sync(0xffffffffu, dot, o);
    if (l16 == 0) out[e] = dot;
}

// ---------------------------------------------------------------------------
extern "C" void kernel_launch(void* const* d_in, const int* in_sizes, int n_in,
                              void* d_out, int out_size)
{
    const int*   nodeIdx = (const int*)  d_in[0];
    const float* attn    = (const float*)d_in[1];
    const int*   eli     = (const int*)  d_in[2];
    const float* emb     = (const float*)d_in[3];
    const float* W1      = (const float*)d_in[4];
    const float* b1      = (const float*)d_in[5];
    const float* W2      = (const float*)d_in[6];
    const float* b2      = (const float*)d_in[7];
    float* out = (float*)d_out;
    const int nPred = in_sizes[2] / 2;

    float *pDis, *pH, *pPart;
    __half *pAf, *pBf;
    cudaGetSymbolAddress((void**)&pDis,  g_dis);
    cudaGetSymbolAddress((void**)&pH,    g_H);
    cudaGetSymbolAddress((void**)&pPart, g_part);
    cudaGetSymbolAddress((void**)&pAf,   g_Af);
    cudaGetSymbolAddress((void**)&pBf,   g_Bf);

    // smem: 3 stages x (A 32x136 + B 32x(BN+8)) halves
    constexpr int SMEM_W = 3 * (32 * 136 + 32 * (256 + 8)) * 2;  // 76800 B (tc2)
    constexpr int SMEM_N = 3 * (32 * 136 + 32 * (128 + 8)) * 2;  // 52224 B (tc4)
    cudaFuncSetAttribute((const void*)tc_gemm<2, 256, 256, 1>,
                         cudaFuncAttributeMaxDynamicSharedMemorySize, SMEM_W);
    cudaFuncSetAttribute((const void*)tc_gemm<4, 128, 128, 2>,
                         cudaFuncAttributeMaxDynamicSharedMemorySize, SMEM_N);

    // 1) convert + deg (fused), then dis
    convert_deg_kernel<<<dim3(8, 128), 256>>>(attn);
    dis_kernel<<<N_NODES / 256, 256>>>();

    // 2) P (fp16 x 2^14) = dis ⊙ (emb[nodeIdx] @ W1)
    simt_gemm<128, 64, 16, 8, 8, true>
        <<<dim3(HID_C / 64, N_NODES / 128), 128>>>(
            emb, E_DIM_C, W1, pBf, pDis, nodeIdx, N_NODES, HID_C, E_DIM_C);

    // 3) H partials = w^T @ P'   split-K=2, BN=256, 64x64 warp tile
    tc_gemm<2, 256, 256, 1>
        <<<dim3(HID_C / 256, N_NODES / 128, 2), 256, SMEM_W>>>(
            pAf, pBf, pPart, N_NODES, HID_C, N_NODES);
    reduce_epi_h_kernel<<<(N_NODES * HID_C / 4 + 255) / 256, 256>>>(pPart, b1);

    // 4) Q (fp16 x 2^14) = dis ⊙ (H @ W2)
    simt_gemm<128, 64, 16, 8, 8, false>
        <<<dim3(OUT_C / 64, N_NODES / 128), 128>>>(
            pH, HID_C, W2, pBf, pDis, nullptr, N_NODES, OUT_C, HID_C);

    // 5) Z partials = w^T @ Q'   split-K=4, BN=128, 64x64 warp tile (128 thr)
    tc_gemm<4, 128, 128, 2>
        <<<dim3(OUT_C / 128, N_NODES / 128, 4), 128, SMEM_N>>>(
            pAf, pBf, pPart, N_NODES, OUT_C, N_NODES);
    reduce_epi_z_kernel<<<(N_NODES * OUT_C / 4 + 255) / 256, 256>>>(pPart, b2);

    // 6) decode (16 lanes per edge)
    decode_kernel<<<(nPred * 16 + 255) / 256, 256>>>(eli, out, nPred);
}

// round 15
// speedup vs baseline: 1.8951x; 1.0419x over previous
#include <cuda_runtime.h>
#include <cuda_fp16.h>
#include <cstdint>

// ---------------------------------------------------------------------------
// Round 14: both TC GEMMs use the proven 128-thr / BN=128 / 64x64-warp-tile
// / 2-CTA-per-SM shape (R13's tc4 config). tc2: grid 2x64x2 = 256 CTAs.
//   A (relu(attn)) -> fp16 plane;  B (P/Q) -> fp16 plane scaled 2^14.
//   Z fp16 (L2-resident); 16-lane decode.
// ---------------------------------------------------------------------------

static constexpr int N_NODES = 8192;
static constexpr int E_DIM_C = 256;
static constexpr int HID_C   = 256;
static constexpr int OUT_C   = 128;
static constexpr float B_SCALE     = 16384.0f;       // 2^14
static constexpr float B_INV_SCALE = 1.0f / 16384.0f;

__device__ float   g_degp[128 * N_NODES];
__device__ float   g_dis [N_NODES];
__device__ __half  g_Af  [(size_t)N_NODES * N_NODES];   // 128 MB fp16 relu(attn)
__device__ __half  g_Bf  [N_NODES * HID_C];             // P/Q (scaled fp16)
__device__ float   g_H   [N_NODES * HID_C];
__device__ __half  g_Zh  [N_NODES * OUT_C];             // 2 MB fp16 Z
__device__ float   g_part[4 * N_NODES * OUT_C];         // split-K partials

// ---------------------------------------------------------------------------
__global__ void convert_deg_kernel(const float* __restrict__ attn)
{
    int c4 = blockIdx.x * blockDim.x + threadIdx.x;
    int r0 = blockIdx.y * 64;
    float4 s = make_float4(0.f, 0.f, 0.f, 0.f);
    const float4* a = reinterpret_cast<const float4*>(attn);
    #pragma unroll 4
    for (int r = 0; r < 64; ++r) {
        size_t row = r0 + r;
        float4 v = a[row * (N_NODES / 4) + c4];
        v.x = fmaxf(v.x, 0.f); v.y = fmaxf(v.y, 0.f);
        v.z = fmaxf(v.z, 0.f); v.w = fmaxf(v.w, 0.f);
        s.x += v.x; s.y += v.y; s.z += v.z; s.w += v.w;
        __half2 h0 = __floats2half2_rn(v.x, v.y);
        __half2 h1 = __floats2half2_rn(v.z, v.w);
        uint2 packed;
        packed.x = *reinterpret_cast<uint32_t*>(&h0);
        packed.y = *reinterpret_cast<uint32_t*>(&h1);
        reinterpret_cast<uint2*>(g_Af)[(row * N_NODES) / 4 + c4] = packed;
    }
    reinterpret_cast<float4*>(g_degp)[blockIdx.y * (N_NODES / 4) + c4] = s;
}

__global__ void dis_kernel()
{
    int col = blockIdx.x * blockDim.x + threadIdx.x;
    float s = 0.f;
    #pragma unroll
    for (int r = 0; r < 128; ++r) s += g_degp[(size_t)r * N_NODES + col];
    g_dis[col] = (s > 0.f) ? rsqrtf(s) : 0.f;
}

// ---------------------------------------------------------------------------
__device__ __forceinline__ void ldsm_x4_t(uint32_t& r0, uint32_t& r1,
                                          uint32_t& r2, uint32_t& r3, uint32_t addr)
{
    asm volatile("ldmatrix.sync.aligned.m8n8.x4.trans.shared.b16 {%0,%1,%2,%3}, [%4];"
                 : "=r"(r0), "=r"(r1), "=r"(r2), "=r"(r3) : "r"(addr));
}

__device__ __forceinline__ void mma16816h(float* d, const uint32_t* a, const uint32_t* b)
{
    asm volatile("mma.sync.aligned.m16n8k16.row.col.f32.f16.f16.f32 "
                 "{%0,%1,%2,%3}, {%4,%5,%6,%7}, {%8,%9}, {%0,%1,%2,%3};"
                 : "+f"(d[0]), "+f"(d[1]), "+f"(d[2]), "+f"(d[3])
                 : "r"(a[0]), "r"(a[1]), "r"(a[2]), "r"(a[3]), "r"(b[0]), "r"(b[1]));
}

__device__ __forceinline__ void cpasync16(uint32_t smem, const void* gmem)
{
    asm volatile("cp.async.cg.shared.global [%0], [%1], 16;" :: "r"(smem), "l"(gmem));
}

// ---------------------------------------------------------------------------
// TC GEMM, 64x64 warp tile, 128 threads (2x2 warps), BM=128, BN=128, BK=32.
//   Af: [K, M] fp16, Bf: [K, Ntot] fp16 (pre-scaled). 3-stage cp.async,
//   2 CTAs/SM.
// ---------------------------------------------------------------------------
template<int SPLITK>
__global__ __launch_bounds__(128, 2)
void tc_gemm(const __half* __restrict__ Afg,
             const __half* __restrict__ Bfg,
             float* __restrict__ Cpart, int M, int Ntot, int K)
{
    constexpr int BM = 128, BN = 128, BK = 32;
    constexpr int AP = 136;
    constexpr int BP = BN + 8;
    constexpr int ASTG = BK * AP;
    constexpr int BSTG = BK * BP;
    constexpr int NSTAGE = 3;
    constexpr int NT = 128;
    constexpr int CA = 512 / NT;                  // 4 A-chunks per thread
    constexpr int CB = (4 * BN) / NT;             // 4 B-chunks per thread
    constexpr int BC8 = BN / 8;

    extern __shared__ __half smheap[];
    auto planeA = [&](int s) { return smheap + s * (ASTG + BSTG); };
    auto planeB = [&](int s) { return smheap + s * (ASTG + BSTG) + ASTG; };

    const int tid  = threadIdx.x;
    const int lane = tid & 31;
    const int wid  = tid >> 5;
    const int wm   = (wid >> 1) * 64;             // 2x2 warp grid
    const int wn   = (wid & 1) * 64;
    const int m0   = blockIdx.y * BM;
    const int n0   = blockIdx.x * BN;
    const int Ksp  = K / SPLITK;
    const int kB   = blockIdx.z * Ksp;
    const int KT   = Ksp / BK;

    float acc[4][8][4];
    #pragma unroll
    for (int i = 0; i < 4; ++i)
        #pragma unroll
        for (int j = 0; j < 8; ++j)
            #pragma unroll
            for (int q = 0; q < 4; ++q) acc[i][j][q] = 0.f;

    auto issue = [&](int kt, int s) {
        int kg = kB + kt * BK;
        uint32_t ab = (uint32_t)__cvta_generic_to_shared(planeA(s));
        uint32_t bb = (uint32_t)__cvta_generic_to_shared(planeB(s));
        #pragma unroll
        for (int v = 0; v < CA; ++v) {
            int idx = tid + v * NT;
            int row = idx >> 4;
            int c16 = idx & 15;
            cpasync16(ab + row * (AP * 2) + c16 * 16,
                      Afg + (size_t)(kg + row) * M + m0 + c16 * 8);
        }
        #pragma unroll
        for (int v = 0; v < CB; ++v) {
            int idx = tid + v * NT;
            int row = idx / BC8;
            int cc  = idx % BC8;
            cpasync16(bb + row * (BP * 2) + cc * 16,
                      Bfg + (size_t)(kg + row) * Ntot + n0 + cc * 8);
        }
        asm volatile("cp.async.commit_group;");
    };

    const int aRow = (lane & 7) + ((lane >> 4) & 1) * 8;
    const int aCol = wm + ((lane >> 3) & 1) * 8;
    const int bRow = (lane & 7) + ((lane >> 3) & 1) * 8;
    const int bCol = wn + ((lane >> 4) & 1) * 8;

    auto compute = [&](int s) {
        uint32_t ab = (uint32_t)__cvta_generic_to_shared(planeA(s));
        uint32_t bb = (uint32_t)__cvta_generic_to_shared(planeB(s));
        #pragma unroll
        for (int k16 = 0; k16 < 2; ++k16) {
            int k0 = k16 * 16;
            uint32_t bf[8][2];
            #pragma unroll
            for (int p = 0; p < 4; ++p) {
                uint32_t off = ((k0 + bRow) * BP + bCol + p * 16) * 2;
                uint32_t r0, r1, r2, r3;
                ldsm_x4_t(r0, r1, r2, r3, bb + off);
                bf[2 * p][0] = r0; bf[2 * p][1] = r1;
                bf[2 * p + 1][0] = r2; bf[2 * p + 1][1] = r3;
            }
            #pragma unroll
            for (int mi = 0; mi < 4; ++mi) {
                uint32_t af[4];
                uint32_t off = ((k0 + aRow) * AP + aCol + mi * 16) * 2;
                ldsm_x4_t(af[0], af[1], af[2], af[3], ab + off);
                #pragma unroll
                for (int ni = 0; ni < 8; ++ni)
                    mma16816h(acc[mi][ni], af, bf[ni]);
            }
        }
    };

    issue(0, 0);
    if (KT > 1) issue(1, 1);
    if (KT > 2) issue(2, 2);

    for (int kt = 0; kt < KT; ++kt) {
        asm volatile("cp.async.wait_group %0;" :: "n"(NSTAGE - 2));
        __syncthreads();
        compute(kt % NSTAGE);
        __syncthreads();
        if (kt + NSTAGE < KT) {
            issue(kt + NSTAGE, kt % NSTAGE);
        } else if (kt + 1 < KT) {
            asm volatile("cp.async.commit_group;");
        }
    }

    float* Cp = Cpart + (size_t)blockIdx.z * M * Ntot;
    const int rB = m0 + wm + (lane >> 2);
    const int cB = n0 + wn + (lane & 3) * 2;
    #pragma unroll
    for (int mi = 0; mi < 4; ++mi)
        #pragma unroll
        for (int ni = 0; ni < 8; ++ni) {
            int r = rB + mi * 16;
            int c = cB + ni * 8;
            *reinterpret_cast<float2*>(Cp + (size_t)r * Ntot + c) =
                make_float2(acc[mi][ni][0], acc[mi][ni][1]);
            *reinterpret_cast<float2*>(Cp + (size_t)(r + 8) * Ntot + c) =
                make_float2(acc[mi][ni][2], acc[mi][ni][3]);
        }
}

// ---------------------------------------------------------------------------
__global__ void reduce_epi_h_kernel(const float* __restrict__ part,
                                    const float* __restrict__ bias)
{
    int i4 = blockIdx.x * blockDim.x + threadIdx.x;
    constexpr int N = HID_C;
    constexpr int MN4 = N_NODES * N / 4;
    if (i4 >= MN4) return;
    const float4* p = reinterpret_cast<const float4*>(part);
    float4 s = p[i4];
    float4 v = p[i4 + (size_t)MN4];
    s.x += v.x; s.y += v.y; s.z += v.z; s.w += v.w;
    int row = (i4 * 4) / N;
    int col = (i4 * 4) % N;
    float sc = g_dis[row] * B_INV_SCALE;
    float4 bb = *reinterpret_cast<const float4*>(bias + col);
    float4 r;
    r.x = fmaxf(s.x * sc + bb.x, 0.f);
    r.y = fmaxf(s.y * sc + bb.y, 0.f);
    r.z = fmaxf(s.z * sc + bb.z, 0.f);
    r.w = fmaxf(s.w * sc + bb.w, 0.f);
    reinterpret_cast<float4*>(g_H)[i4] = r;
}

__global__ void reduce_epi_z_kernel(const float* __restrict__ part,
                                    const float* __restrict__ bias)
{
    int i4 = blockIdx.x * blockDim.x + threadIdx.x;
    constexpr int N = OUT_C;
    constexpr int MN4 = N_NODES * N / 4;
    if (i4 >= MN4) return;
    const float4* p = reinterpret_cast<const float4*>(part);
    float4 s = p[i4];
    #pragma unroll
    for (int sp = 1; sp < 4; ++sp) {
        float4 v = p[i4 + (size_t)sp * MN4];
        s.x += v.x; s.y += v.y; s.z += v.z; s.w += v.w;
    }
    int row = (i4 * 4) / N;
    int col = (i4 * 4) % N;
    float sc = g_dis[row] * B_INV_SCALE;
    float4 bb = *reinterpret_cast<const float4*>(bias + col);
    __half2 h0 = __floats2half2_rn(s.x * sc + bb.x, s.y * sc + bb.y);
    __half2 h1 = __floats2half2_rn(s.z * sc + bb.z, s.w * sc + bb.w);
    uint2 packed;
    packed.x = *reinterpret_cast<uint32_t*>(&h0);
    packed.y = *reinterpret_cast<uint32_t*>(&h1);
    reinterpret_cast<uint2*>(g_Zh)[i4] = packed;
}

// ---------------------------------------------------------------------------
template<int BM, int BN, int BK, int TM, int TN, bool GATHER_A>
__global__ __launch_bounds__((BM / TM) * (BN / TN))
void simt_gemm(const float* __restrict__ A, int lda,
               const float* __restrict__ B,
               __half* __restrict__ Cf,
               const float* __restrict__ rowScale,
               const int* __restrict__ gatherIdx,
               int M, int N, int K)
{
    constexpr int NT   = (BM / TM) * (BN / TN);
    constexpr int APAD = 4;
    constexpr int AV   = (BM * BK) / (4 * NT);
    constexpr int BV   = (BK * BN) / (4 * NT);

    __shared__ float As[BK][BM + APAD];
    __shared__ float Bs[BK][BN];

    const int tid = threadIdx.x;
    const int tx  = tid % (BN / TN);
    const int ty  = tid / (BN / TN);
    const int m0  = blockIdx.y * BM;
    const int n0  = blockIdx.x * BN;

    float4 areg[AV], breg[BV];
    float acc[TM][TN];
    #pragma unroll
    for (int i = 0; i < TM; ++i)
        #pragma unroll
        for (int j = 0; j < TN; ++j) acc[i][j] = 0.f;

    auto loadA = [&](int k0) {
        #pragma unroll
        for (int v = 0; v < AV; ++v) {
            int idx = tid + v * NT;
            int m  = idx / (BK / 4);
            int kq = idx % (BK / 4);
            int row = GATHER_A ? gatherIdx[m0 + m] : (m0 + m);
            areg[v] = *reinterpret_cast<const float4*>(A + (size_t)row * lda + (k0 + kq * 4));
        }
    };
    auto storeA = [&]() {
        #pragma unroll
        for (int v = 0; v < AV; ++v) {
            int idx = tid + v * NT;
            int m  = idx / (BK / 4);
            int kq = idx % (BK / 4);
            As[kq * 4 + 0][m] = areg[v].x;
            As[kq * 4 + 1][m] = areg[v].y;
            As[kq * 4 + 2][m] = areg[v].z;
            As[kq * 4 + 3][m] = areg[v].w;
        }
    };
    auto loadB = [&](int k0) {
        #pragma unroll
        for (int v = 0; v < BV; ++v) {
            int idx = tid + v * NT;
            int k  = idx / (BN / 4);
            int n4 = idx % (BN / 4);
            breg[v] = *reinterpret_cast<const float4*>(B + (size_t)(k0 + k) * N + (n0 + n4 * 4));
        }
    };
    auto storeB = [&]() {
        #pragma unroll
        for (int v = 0; v < BV; ++v) {
            int idx = tid + v * NT;
            int k  = idx / (BN / 4);
            int n4 = idx % (BN / 4);
            *reinterpret_cast<float4*>(&Bs[k][n4 * 4]) = breg[v];
        }
    };

    loadA(0); loadB(0);
    storeA(); storeB();
    __syncthreads();

    const int KT = K / BK;
    for (int kt = 0; kt < KT; ++kt) {
        if (kt + 1 < KT) { loadA((kt + 1) * BK); loadB((kt + 1) * BK); }
        #pragma unroll
        for (int kk = 0; kk < BK; ++kk) {
            float a[TM], b[TN];
            #pragma unroll
            for (int i = 0; i < TM; i += 4) {
                float4 t = *reinterpret_cast<const float4*>(&As[kk][ty * TM + i]);
                a[i] = t.x; a[i + 1] = t.y; a[i + 2] = t.z; a[i + 3] = t.w;
            }
            #pragma unroll
            for (int j = 0; j < TN; j += 4) {
                float4 t = *reinterpret_cast<const float4*>(&Bs[kk][tx * TN + j]);
                b[j] = t.x; b[j + 1] = t.y; b[j + 2] = t.z; b[j + 3] = t.w;
            }
            #pragma unroll
            for (int i = 0; i < TM; ++i)
                #pragma unroll
                for (int j = 0; j < TN; ++j)
                    acc[i][j] = fmaf(a[i], b[j], acc[i][j]);
        }
        if (kt + 1 < KT) {
            __syncthreads();
            storeA(); storeB();
            __syncthreads();
        }
    }

    #pragma unroll
    for (int i = 0; i < TM; ++i) {
        int row = m0 + ty * TM + i;
        float sc = rowScale[row] * B_SCALE;
        #pragma unroll
        for (int j = 0; j < TN; j += 4) {
            int col = n0 + tx * TN + j;
            __half h[4];
            h[0] = __float2half_rn(acc[i][j + 0] * sc);
            h[1] = __float2half_rn(acc[i][j + 1] * sc);
            h[2] = __float2half_rn(acc[i][j + 2] * sc);
            h[3] = __float2half_rn(acc[i][j + 3] * sc);
            reinterpret_cast<uint2*>(Cf)[((size_t)row * N + col) / 4] =
                *reinterpret_cast<uint2*>(h);
        }
    }
}

// ---------------------------------------------------------------------------
// decode: 16 lanes per edge, uint4 loads of fp16 Z.
// ---------------------------------------------------------------------------
__global__ __launch_bounds__(256)
void decode_kernel(const int* __restrict__ eli,
                   float* __restrict__ out, int nPred)
{
    int g = blockIdx.x * blockDim.x + threadIdx.x;
    int e = g >> 4;
    int l16 = threadIdx.x & 15;
    if (e >= nPred) return;
    int s = __ldg(eli + e);
    int d = __ldg(eli + nPred + e);
    const uint4* zs = reinterpret_cast<const uint4*>(g_Zh + (size_t)s * OUT_C);
    const uint4* zd = reinterpret_cast<const uint4*>(g_Zh + (size_t)d * OUT_C);
    uint4 ar = __ldg(zs + l16);
    uint4 br = __ldg(zd + l16);
    float dot = 0.f;
    const uint32_t* au = &ar.x;
    const uint32_t* bu = &br.x;
    #pragma unroll
    for (int q = 0; q < 4; ++q) {
        __half2 ah = *reinterpret_cast<const __half2*>(&au[q]);
        __half2 bh = *reinterpret_cast<const __half2*>(&bu[q]);
        float2 af = __half22float2(ah);
        float2 bf = __half22float2(bh);
        dot += af.x * bf.x + af.y * bf.y;
    }
    #pragma unroll
    for (int o = 8; o; o >>= 1) dot += __shfl_xor_sync(0xffffffffu, dot, o);
    if (l16 == 0) out[e] = dot;
}

// ---------------------------------------------------------------------------
extern "C" void kernel_launch(void* const* d_in, const int* in_sizes, int n_in,
                              void* d_out, int out_size)
{
    const int*   nodeIdx = (const int*)  d_in[0];
    const float* attn    = (const float*)d_in[1];
    const int*   eli     = (const int*)  d_in[2];
    const float* emb     = (const float*)d_in[3];
    const float* W1      = (const float*)d_in[4];
    const float* b1      = (const float*)d_in[5];
    const float* W2      = (const float*)d_in[6];
    const float* b2      = (const float*)d_in[7];
    float* out = (float*)d_out;
    const int nPred = in_sizes[2] / 2;

    float *pDis, *pH, *pPart;
    __half *pAf, *pBf;
    cudaGetSymbolAddress((void**)&pDis,  g_dis);
    cudaGetSymbolAddress((void**)&pH,    g_H);
    cudaGetSymbolAddress((void**)&pPart, g_part);
    cudaGetSymbolAddress((void**)&pAf,   g_Af);
    cudaGetSymbolAddress((void**)&pBf,   g_Bf);

    // smem: 3 stages x (A 32x136 + B 32x136) halves = 52224 B
    constexpr int TC_SMEM = 3 * (32 * 136 + 32 * 136) * 2;
    cudaFuncSetAttribute(tc_gemm<2>, cudaFuncAttributeMaxDynamicSharedMemorySize, TC_SMEM);
    cudaFuncSetAttribute(tc_gemm<4>, cudaFuncAttributeMaxDynamicSharedMemorySize, TC_SMEM);

    // 1) convert + deg (fused), then dis
    convert_deg_kernel<<<dim3(8, 128), 256>>>(attn);
    dis_kernel<<<N_NODES / 256, 256>>>();

    // 2) P (fp16 x 2^14) = dis ⊙ (emb[nodeIdx] @ W1)
    simt_gemm<128, 64, 16, 8, 8, true>
        <<<dim3(HID_C / 64, N_NODES / 128), 128>>>(
            emb, E_DIM_C, W1, pBf, pDis, nodeIdx, N_NODES, HID_C, E_DIM_C);

    // 3) H partials = w^T @ P'   split-K=2, 128 thr, BN=128, 64x64 warp tile
    tc_gemm<2><<<dim3(HID_C / 128, N_NODES / 128, 2), 128, TC_SMEM>>>(
        pAf, pBf, pPart, N_NODES, HID_C, N_NODES);
    reduce_epi_h_kernel<<<(N_NODES * HID_C / 4 + 255) / 256, 256>>>(pPart, b1);

    // 4) Q (fp16 x 2^14) = dis ⊙ (H @ W2)
    simt_gemm<128, 64, 16, 8, 8, false>
        <<<dim3(OUT_C / 64, N_NODES / 128), 128>>>(
            pH, HID_C, W2, pBf, pDis, nullptr, N_NODES, OUT_C, HID_C);

    // 5) Z partials = w^T @ Q'   split-K=4, same shape
    tc_gemm<4><<<dim3(OUT_C / 128, N_NODES / 128, 4), 128, TC_SMEM>>>(
        pAf, pBf, pPart, N_NODES, OUT_C, N_NODES);
    reduce_epi_z_kernel<<<(N_NODES * OUT_C / 4 + 255) / 256, 256>>>(pPart, b2);

    // 6) decode (16 lanes per edge)
    decode_kernel<<<(nPred * 16 + 255) / 256, 256>>>(eli, out, nPred);
}